// round 6
// baseline (speedup 1.0000x reference)
#include <cuda_runtime.h>
#include <cuda_fp16.h>
#include <math_constants.h>

#define MAXN 131072
#define MAXB 32
#define EPSV 1e-5f

// ---------------- scratch (static device globals; no allocation) ----------------
__device__ __align__(16) __half g_mlph[256 * MAXN];   // mlp_feat fp16 [256][N] (64 MB)
__device__ __align__(16) __half g_y2h [512 * MAXN];   // pre-BN2 y2 fp16 [512][N] (128 MB)
__device__ __align__(16) __half g_W2a_h[512 * 512];
__device__ __align__(16) __half g_W2b_h[1024 * 512];
__device__ float    g_psum[512 * 1024];   // per-(c, n-block) partial sums
__device__ float    g_psq [512 * 1024];
__device__ float    g_xpart[128 * 9];
__device__ float    g_Wf1[128 * 3];
__device__ float    g_bf1[128];
__device__ float    g_a2[512];
__device__ float    g_c2[512];
__device__ unsigned g_pool1u[MAXB * 256];
__device__ __half   g_pool1h[MAXB * 256];
__device__ unsigned g_pool2u[MAXB * 1024];
__device__ int      g_off[MAXB + 1];
__device__ unsigned char g_segid[MAXN];

// monotonic float<->uint key for exact atomic max
__device__ __forceinline__ unsigned fkey(float f) {
    unsigned u = __float_as_uint(f);
    return (u & 0x80000000u) ? ~u : (u | 0x80000000u);
}
__device__ __forceinline__ float funkey(unsigned k) {
    return (k & 0x80000000u) ? __uint_as_float(k & 0x7fffffffu)
                             : __uint_as_float(~k);
}

__device__ __forceinline__ unsigned smem_u32(const void* p) {
    return (unsigned)__cvta_generic_to_shared(p);
}
__device__ __forceinline__ void ldsm_x4(unsigned* r, unsigned addr) {
    asm volatile("ldmatrix.sync.aligned.m8n8.x4.shared.b16 {%0,%1,%2,%3},[%4];"
                 : "=r"(r[0]), "=r"(r[1]), "=r"(r[2]), "=r"(r[3]) : "r"(addr));
}
__device__ __forceinline__ void ldsm_x4_t(unsigned* r, unsigned addr) {
    asm volatile("ldmatrix.sync.aligned.m8n8.x4.trans.shared.b16 {%0,%1,%2,%3},[%4];"
                 : "=r"(r[0]), "=r"(r[1]), "=r"(r[2]), "=r"(r[3]) : "r"(addr));
}
__device__ __forceinline__ void mma16816(float* d, const unsigned* a, unsigned b0, unsigned b1) {
    asm volatile("mma.sync.aligned.m16n8k16.row.col.f32.f16.f16.f32 "
                 "{%0,%1,%2,%3},{%4,%5,%6,%7},{%8,%9},{%0,%1,%2,%3};"
                 : "+f"(d[0]), "+f"(d[1]), "+f"(d[2]), "+f"(d[3])
                 : "r"(a[0]), "r"(a[1]), "r"(a[2]), "r"(a[3]), "r"(b0), "r"(b1));
}

// ---------------- K0: offsets + pool init ----------------
__global__ void k_init(const int* npts, int B) {
    int tid = blockIdx.x * blockDim.x + threadIdx.x;
    if (blockIdx.x == 0 && threadIdx.x == 0) {
        int acc = 0; g_off[0] = 0;
        for (int b = 0; b < B; b++) { acc += npts[b]; g_off[b + 1] = acc; }
    }
    int stride = gridDim.x * blockDim.x;
    for (int i = tid; i < MAXB * 256;  i += stride) g_pool1u[i] = 0u;
    for (int i = tid; i < MAXB * 1024; i += stride) g_pool2u[i] = 0u;
}

__global__ void k_segid(int N, int B) {
    int n = blockIdx.x * blockDim.x + threadIdx.x;
    if (n >= N) return;
    int s = 0;
    while (s + 1 < B && g_off[s + 1] <= n) s++;
    g_segid[n] = (unsigned char)s;
}

__global__ void k_convW(const float* __restrict__ W2a, const float* __restrict__ W2b) {
    int i = blockIdx.x * blockDim.x + threadIdx.x;
    if (i < 512 * 512)  g_W2a_h[i] = __float2half_rn(W2a[i]);
    if (i < 1024 * 512) g_W2b_h[i] = __float2half_rn(W2b[i]);
}

// ---------------- K1a: x moments ----------------
__global__ void k_xstats(const float* __restrict__ x, int N) {
    float s0 = 0, s1 = 0, s2 = 0, q0 = 0, q1 = 0, q2 = 0, q3 = 0, q4 = 0, q5 = 0;
    int stride = gridDim.x * blockDim.x;
    for (int n = blockIdx.x * blockDim.x + threadIdx.x; n < N; n += stride) {
        float a = x[n], b = x[N + n], c = x[2 * N + n];
        s0 += a; s1 += b; s2 += c;
        q0 += a * a; q1 += a * b; q2 += a * c; q3 += b * b; q4 += b * c; q5 += c * c;
    }
    __shared__ float rb[256];
    float vals[9] = {s0, s1, s2, q0, q1, q2, q3, q4, q5};
    for (int v = 0; v < 9; v++) {
        rb[threadIdx.x] = vals[v];
        __syncthreads();
        for (int st = 128; st > 0; st >>= 1) {
            if (threadIdx.x < st) rb[threadIdx.x] += rb[threadIdx.x + st];
            __syncthreads();
        }
        if (threadIdx.x == 0) g_xpart[blockIdx.x * 9 + v] = rb[0];
        __syncthreads();
    }
}

// ---------------- K1b: fold BN1 into conv1a ----------------
__global__ void k_fold1(const float* __restrict__ W1a, const float* __restrict__ b1a,
                        const float* __restrict__ g1,  const float* __restrict__ be1,
                        int N, int nblocks) {
    __shared__ double S[9];
    __shared__ float mu[3], C[3][3];
    if (threadIdx.x < 9) {
        double a = 0;
        for (int b = 0; b < nblocks; b++) a += (double)g_xpart[b * 9 + threadIdx.x];
        S[threadIdx.x] = a;
    }
    __syncthreads();
    if (threadIdx.x == 0) {
        double invN = 1.0 / (double)N;
        double m0 = S[0] * invN, m1 = S[1] * invN, m2 = S[2] * invN;
        mu[0] = (float)m0; mu[1] = (float)m1; mu[2] = (float)m2;
        C[0][0] = (float)(S[3] * invN - m0 * m0);
        C[0][1] = (float)(S[4] * invN - m0 * m1);
        C[0][2] = (float)(S[5] * invN - m0 * m2);
        C[1][1] = (float)(S[6] * invN - m1 * m1);
        C[1][2] = (float)(S[7] * invN - m1 * m2);
        C[2][2] = (float)(S[8] * invN - m2 * m2);
        C[1][0] = C[0][1]; C[2][0] = C[0][2]; C[2][1] = C[1][2];
    }
    __syncthreads();
    int c = threadIdx.x;
    float w0 = W1a[c * 3], w1 = W1a[c * 3 + 1], w2 = W1a[c * 3 + 2];
    float mean1 = w0 * mu[0] + w1 * mu[1] + w2 * mu[2] + b1a[c];
    float var1 = w0 * w0 * C[0][0] + w1 * w1 * C[1][1] + w2 * w2 * C[2][2]
               + 2.f * (w0 * w1 * C[0][1] + w0 * w2 * C[0][2] + w1 * w2 * C[1][2]);
    float a = g1[c] * rsqrtf(var1 + EPSV);
    g_Wf1[c * 3 + 0] = a * w0;
    g_Wf1[c * 3 + 1] = a * w1;
    g_Wf1[c * 3 + 2] = a * w2;
    g_bf1[c] = a * (b1a[c] - mean1) + be1[c];
}

// ---------------- K2: fused conv1a+BN1+ReLU+conv1b + seg-max(pool1) ----------------
__global__ void __launch_bounds__(256) k_stage1(const float* __restrict__ x,
                                                const float* __restrict__ W1b,
                                                const float* __restrict__ b1b,
                                                int N, int B) {
    __shared__ float xs[3 * 64];
    __shared__ float hs[128 * 64];
    __shared__ int s_segA, s_bnd;
    int tid = threadIdx.x;
    int n0 = blockIdx.x * 64;
    if (tid < 192) xs[tid] = x[(tid >> 6) * N + n0 + (tid & 63)];
    if (tid == 0) {
        int s = 0;
        while (s + 1 < B && g_off[s + 1] <= n0) s++;
        s_segA = s; s_bnd = g_off[s + 1];
    }
    __syncthreads();
    #pragma unroll
    for (int i = 0; i < 32; i++) {
        int e = tid + i * 256;
        int c = e >> 6, p = e & 63;
        float h = g_bf1[c] + g_Wf1[c * 3] * xs[p]
                + g_Wf1[c * 3 + 1] * xs[64 + p]
                + g_Wf1[c * 3 + 2] * xs[128 + p];
        hs[e] = fmaxf(h, 0.f);
    }
    __syncthreads();
    float acc[64];
    #pragma unroll
    for (int p = 0; p < 64; p++) acc[p] = 0.f;
    const float* wrow = W1b + tid * 128;
    for (int k0 = 0; k0 < 128; k0 += 16) {
        float4 w4[4];
        w4[0] = *(const float4*)(wrow + k0);
        w4[1] = *(const float4*)(wrow + k0 + 4);
        w4[2] = *(const float4*)(wrow + k0 + 8);
        w4[3] = *(const float4*)(wrow + k0 + 12);
        const float* wv = (const float*)w4;
        #pragma unroll
        for (int kk = 0; kk < 16; kk++) {
            float w = wv[kk];
            const float4* hp = (const float4*)&hs[(k0 + kk) * 64];
            #pragma unroll
            for (int p4 = 0; p4 < 16; p4++) {
                float4 hv = hp[p4];
                acc[p4 * 4 + 0] += w * hv.x;
                acc[p4 * 4 + 1] += w * hv.y;
                acc[p4 * 4 + 2] += w * hv.z;
                acc[p4 * 4 + 3] += w * hv.w;
            }
        }
    }
    float bb = b1b[tid];
    float mA = -CUDART_INF_F, mB = -CUDART_INF_F;
    int bnd = s_bnd;
    __half* dst = &g_mlph[(size_t)tid * N + n0];
    #pragma unroll
    for (int p = 0; p < 64; p++) {
        float v = acc[p] + bb;
        acc[p] = v;
        if (n0 + p < bnd) mA = fmaxf(mA, v); else mB = fmaxf(mB, v);
    }
    #pragma unroll
    for (int p2 = 0; p2 < 32; p2++) {
        *(__half2*)&dst[p2 * 2] = __floats2half2_rn(acc[2 * p2], acc[2 * p2 + 1]);
    }
    atomicMax(&g_pool1u[s_segA * 256 + tid], fkey(mA));
    if (bnd < n0 + 64) atomicMax(&g_pool1u[(s_segA + 1) * 256 + tid], fkey(mB));
}

__global__ void k_decode1(int B) {
    int i = blockIdx.x * blockDim.x + threadIdx.x;
    if (i < B * 256) g_pool1h[i] = __float2half_rn(funkey(g_pool1u[i]));
}

// ---------------- tensor-core GEMMs ----------------
// MODE 0: y2 = W2a * [mlp;sym] + b2a, epilogue: store y2 fp16 + BN2 stat partials
// MODE 1: comb = W2b * relu(a2*y2+c2) + b2b, epilogue: fused segment max
// Tiles: 128 (c) x 256 (n) x 16 (k), 256 threads, warp = 64x64, m16n8k16 fp16 mma.
template<int MODE>
__global__ void __launch_bounds__(256) k_mma(const float* __restrict__ bias,
                                             int N, int B) {
    __shared__ __align__(16) __half As[2][128][24];
    __shared__ __align__(16) __half Bs[2][16][264];
    __shared__ float s_red[128][4];

    const int tid = threadIdx.x, lane = tid & 31, wid = tid >> 5;
    const int wm = wid & 1, wn = wid >> 1;
    const int quad = lane >> 2, qlane = lane & 3;
    const int n0 = blockIdx.x * 256;
    const int c0 = blockIdx.y * 128;

    const __half* __restrict__ Aw = (MODE == 0 ? g_W2a_h : g_W2b_h);
    const __half* AglobBase = Aw + (size_t)(c0 + (tid >> 1)) * 512 + (tid & 1) * 8;
    const int kloc = tid >> 4;
    const int ncol = n0 + (tid & 15) * 16;

    // smem addresses for ldmatrix (both buffers)
    unsigned aAddr[2][4], bAddr[2][4];
    #pragma unroll
    for (int s = 0; s < 2; s++) {
        unsigned aBase = smem_u32(&As[s][0][0]);
        unsigned bBase = smem_u32(&Bs[s][0][0]);
        #pragma unroll
        for (int mf = 0; mf < 4; mf++)
            aAddr[s][mf] = aBase + (((wm * 64 + mf * 16 + (lane & 15)) * 24
                                     + (lane >> 4) * 8) << 1);
        #pragma unroll
        for (int np = 0; np < 4; np++)
            bAddr[s][np] = bBase + (((lane & 15) * 264 + wn * 64 + np * 16
                                     + (lane >> 4) * 8) << 1);
    }

    float acc[4][8][4];
    #pragma unroll
    for (int m = 0; m < 4; m++)
        #pragma unroll
        for (int n = 0; n < 8; n++)
            #pragma unroll
            for (int v = 0; v < 4; v++) acc[m][n][v] = 0.f;

    // prefetch helpers
    uint4 pa, pb0, pb1;
    auto loadTiles = [&](int ks) {
        pa = *(const uint4*)(AglobBase + ks * 16);
        int krow = ks * 16 + kloc;
        if (MODE == 0) {
            if (krow < 256) {
                const uint4* p = (const uint4*)(g_mlph + (size_t)krow * N + ncol);
                pb0 = p[0]; pb1 = p[1];
            } else {
                union { __half h[16]; uint4 u[2]; } tb;
                const unsigned char* sp = g_segid + ncol;
                int cs = krow - 256;
                #pragma unroll
                for (int j = 0; j < 16; j++) tb.h[j] = g_pool1h[sp[j] * 256 + cs];
                pb0 = tb.u[0]; pb1 = tb.u[1];
            }
        } else {
            const uint4* p = (const uint4*)(g_y2h + (size_t)krow * N + ncol);
            union { __half h[16]; uint4 u[2]; } src, tb;
            src.u[0] = p[0]; src.u[1] = p[1];
            float a = g_a2[krow], cc = g_c2[krow];
            #pragma unroll
            for (int j = 0; j < 16; j++)
                tb.h[j] = __float2half_rn(fmaxf(__half2float(src.h[j]) * a + cc, 0.f));
            pb0 = tb.u[0]; pb1 = tb.u[1];
        }
    };
    auto storeTiles = [&](int s) {
        *(uint4*)&As[s][tid >> 1][(tid & 1) * 8] = pa;
        *(uint4*)&Bs[s][kloc][(tid & 15) * 16] = pb0;
        *(uint4*)&Bs[s][kloc][(tid & 15) * 16 + 8] = pb1;
    };

    loadTiles(0);
    storeTiles(0);
    __syncthreads();

    for (int ks = 0; ks < 32; ks++) {
        int cur = ks & 1;
        if (ks < 31) loadTiles(ks + 1);
        unsigned af[4][4], bf[4][4];
        #pragma unroll
        for (int mf = 0; mf < 4; mf++) ldsm_x4(af[mf], aAddr[cur][mf]);
        #pragma unroll
        for (int np = 0; np < 4; np++) ldsm_x4_t(bf[np], bAddr[cur][np]);
        #pragma unroll
        for (int mf = 0; mf < 4; mf++)
            #pragma unroll
            for (int nf = 0; nf < 8; nf++)
                mma16816(acc[mf][nf], af[mf], bf[nf >> 1][(nf & 1) * 2],
                         bf[nf >> 1][(nf & 1) * 2 + 1]);
        if (ks < 31) storeTiles(cur ^ 1);
        __syncthreads();
    }

    // ---------------- epilogues ----------------
    if (MODE == 0) {
        int nb = blockIdx.x;
        float sums[4][2], sqs[4][2];
        #pragma unroll
        for (int mf = 0; mf < 4; mf++) {
            int cA = c0 + wm * 64 + mf * 16 + quad;
            int cB = cA + 8;
            float bA = bias[cA], bB = bias[cB];
            float sA = 0, qA = 0, sB = 0, qB = 0;
            #pragma unroll
            for (int nf = 0; nf < 8; nf++) {
                int n = n0 + wn * 64 + nf * 8 + qlane * 2;
                float v0 = acc[mf][nf][0] + bA;
                float v1 = acc[mf][nf][1] + bA;
                float v2 = acc[mf][nf][2] + bB;
                float v3 = acc[mf][nf][3] + bB;
                *(__half2*)&g_y2h[(size_t)cA * N + n] = __floats2half2_rn(v0, v1);
                *(__half2*)&g_y2h[(size_t)cB * N + n] = __floats2half2_rn(v2, v3);
                sA += v0 + v1; qA += v0 * v0 + v1 * v1;
                sB += v2 + v3; qB += v2 * v2 + v3 * v3;
            }
            sums[mf][0] = sA; sums[mf][1] = sB;
            sqs[mf][0] = qA;  sqs[mf][1] = qB;
        }
        #pragma unroll
        for (int mf = 0; mf < 4; mf++)
            #pragma unroll
            for (int h = 0; h < 2; h++) {
                float v = sums[mf][h];
                v += __shfl_xor_sync(0xffffffff, v, 1);
                v += __shfl_xor_sync(0xffffffff, v, 2);
                if (qlane == 0) s_red[wm * 64 + mf * 16 + h * 8 + quad][wn] = v;
            }
        __syncthreads();
        if (tid < 128)
            g_psum[(size_t)(c0 + tid) * 512 + nb] =
                s_red[tid][0] + s_red[tid][1] + s_red[tid][2] + s_red[tid][3];
        __syncthreads();
        #pragma unroll
        for (int mf = 0; mf < 4; mf++)
            #pragma unroll
            for (int h = 0; h < 2; h++) {
                float v = sqs[mf][h];
                v += __shfl_xor_sync(0xffffffff, v, 1);
                v += __shfl_xor_sync(0xffffffff, v, 2);
                if (qlane == 0) s_red[wm * 64 + mf * 16 + h * 8 + quad][wn] = v;
            }
        __syncthreads();
        if (tid < 128)
            g_psq[(size_t)(c0 + tid) * 512 + nb] =
                s_red[tid][0] + s_red[tid][1] + s_red[tid][2] + s_red[tid][3];
    } else {
        __shared__ int s_seg, s_bnd;
        if (tid == 0) {
            int s = g_segid[n0];
            s_seg = s; s_bnd = g_off[s + 1];
        }
        __syncthreads();
        int bnd = s_bnd;
        bool hasB = (bnd < n0 + 256);
        float mA[4][2], mB[4][2];
        #pragma unroll
        for (int mf = 0; mf < 4; mf++) {
            int cA = c0 + wm * 64 + mf * 16 + quad;
            float bA = bias[cA], bB = bias[cA + 8];
            float a0 = -CUDART_INF_F, b0 = -CUDART_INF_F;
            float a1 = -CUDART_INF_F, b1 = -CUDART_INF_F;
            #pragma unroll
            for (int nf = 0; nf < 8; nf++) {
                int n = n0 + wn * 64 + nf * 8 + qlane * 2;
                float v0 = acc[mf][nf][0] + bA;
                float v1 = acc[mf][nf][1] + bA;
                float v2 = acc[mf][nf][2] + bB;
                float v3 = acc[mf][nf][3] + bB;
                if (n < bnd)     a0 = fmaxf(a0, v0); else b0 = fmaxf(b0, v0);
                if (n + 1 < bnd) a0 = fmaxf(a0, v1); else b0 = fmaxf(b0, v1);
                if (n < bnd)     a1 = fmaxf(a1, v2); else b1 = fmaxf(b1, v2);
                if (n + 1 < bnd) a1 = fmaxf(a1, v3); else b1 = fmaxf(b1, v3);
            }
            mA[mf][0] = a0; mA[mf][1] = a1;
            mB[mf][0] = b0; mB[mf][1] = b1;
        }
        #pragma unroll
        for (int mf = 0; mf < 4; mf++)
            #pragma unroll
            for (int h = 0; h < 2; h++) {
                float v = mA[mf][h];
                v = fmaxf(v, __shfl_xor_sync(0xffffffff, v, 1));
                v = fmaxf(v, __shfl_xor_sync(0xffffffff, v, 2));
                if (qlane == 0) s_red[wm * 64 + mf * 16 + h * 8 + quad][wn] = v;
            }
        __syncthreads();
        if (tid < 128) {
            float m = fmaxf(fmaxf(s_red[tid][0], s_red[tid][1]),
                            fmaxf(s_red[tid][2], s_red[tid][3]));
            atomicMax(&g_pool2u[s_seg * 1024 + c0 + tid], fkey(m));
        }
        __syncthreads();
        if (hasB) {
            #pragma unroll
            for (int mf = 0; mf < 4; mf++)
                #pragma unroll
                for (int h = 0; h < 2; h++) {
                    float v = mB[mf][h];
                    v = fmaxf(v, __shfl_xor_sync(0xffffffff, v, 1));
                    v = fmaxf(v, __shfl_xor_sync(0xffffffff, v, 2));
                    if (qlane == 0) s_red[wm * 64 + mf * 16 + h * 8 + quad][wn] = v;
                }
            __syncthreads();
            if (tid < 128) {
                float m = fmaxf(fmaxf(s_red[tid][0], s_red[tid][1]),
                                fmaxf(s_red[tid][2], s_red[tid][3]));
                atomicMax(&g_pool2u[(s_seg + 1) * 1024 + c0 + tid], fkey(m));
            }
        }
    }
}

// ---------------- K4: reduce BN2 stats ----------------
__global__ void k_bn2(const float* __restrict__ g2, const float* __restrict__ be2,
                      int N, int NB) {
    int c = blockIdx.x * blockDim.x + threadIdx.x;
    if (c >= 512) return;
    double s = 0, q = 0;
    for (int nb = 0; nb < NB; nb++) {
        s += (double)g_psum[(size_t)c * 512 + nb];
        q += (double)g_psq[(size_t)c * 512 + nb];
    }
    double mean = s / (double)N;
    double var  = q / (double)N - mean * mean;
    float a = g2[c] * rsqrtf((float)var + EPSV);
    g_a2[c] = a;
    g_c2[c] = be2[c] - (float)mean * a;
}

// ---------------- K6: decode output ----------------
__global__ void k_out(float* __restrict__ out, int B) {
    int i = blockIdx.x * blockDim.x + threadIdx.x;
    if (i < B * 1024) out[i] = funkey(g_pool2u[i]);
}

// ---------------- launch ----------------
extern "C" void kernel_launch(void* const* d_in, const int* in_sizes, int n_in,
                              void* d_out, int out_size) {
    const float* x   = (const float*)d_in[0];
    const int*   np  = (const int*)  d_in[1];
    const float* W1a = (const float*)d_in[2];
    const float* b1a = (const float*)d_in[3];
    const float* g1  = (const float*)d_in[4];
    const float* be1 = (const float*)d_in[5];
    const float* W1b = (const float*)d_in[6];
    const float* b1b = (const float*)d_in[7];
    const float* W2a = (const float*)d_in[8];
    const float* b2a = (const float*)d_in[9];
    const float* g2  = (const float*)d_in[10];
    const float* be2 = (const float*)d_in[11];
    const float* W2b = (const float*)d_in[12];
    const float* b2b = (const float*)d_in[13];
    int N = in_sizes[0] / 3;
    int B = in_sizes[1];
    if (N > MAXN) N = MAXN;

    k_init<<<32, 256>>>(np, B);
    k_segid<<<(N + 255) / 256, 256>>>(N, B);
    k_convW<<<2048, 256>>>(W2a, W2b);
    k_xstats<<<128, 256>>>(x, N);
    k_fold1<<<1, 128>>>(W1a, b1a, g1, be1, N, 128);
    k_stage1<<<N / 64, 256>>>(x, W1b, b1b, N, B);
    k_decode1<<<(B * 256 + 255) / 256, 256>>>(B);
    dim3 g3(N / 256, 4);
    k_mma<0><<<g3, 256>>>(b2a, N, B);
    k_bn2<<<2, 256>>>(g2, be2, N, N / 256);
    dim3 g5(N / 256, 8);
    k_mma<1><<<g5, 256>>>(b2b, N, B);
    k_out<<<(B * 1024 + 255) / 256, 256>>>((float*)d_out, B);
}

// round 8
// speedup vs baseline: 1.3424x; 1.3424x over previous
#include <cuda_runtime.h>
#include <cuda_fp16.h>
#include <math_constants.h>
#include <cstdint>

#define MAXN 131072
#define MAXB 32
#define EPSV 1e-5f

// ---------------- scratch (static device globals; no allocation) ----------------
__device__ __align__(16) __half g_mlph[256 * MAXN];   // mlp_feat fp16 [c][N] (64 MB)
__device__ __align__(16) __half g_symh[256 * MAXN];   // broadcast sym  [c][N] (64 MB)
__device__ __align__(16) __half g_y2h [512 * MAXN];   // y2 fp16 [c][N]; activated in-place (128 MB)
__device__ __align__(16) __half g_W2a_h[512 * 512];
__device__ __align__(16) __half g_W2b_h[1024 * 512];
__device__ float    g_psum[512 * 1024];
__device__ float    g_psq [512 * 1024];
__device__ float    g_xpart[128 * 9];
__device__ float    g_Wf1[128 * 3];
__device__ float    g_bf1[128];
__device__ float    g_a2[512];
__device__ float    g_c2[512];
__device__ unsigned g_pool1u[MAXB * 256];
__device__ __align__(16) __half g_pool1h[MAXB * 256];
__device__ unsigned g_pool2u[MAXB * 1024];
__device__ int      g_off[MAXB + 1];
__device__ __align__(8) unsigned char g_segid[MAXN];

// monotonic float<->uint key for exact atomic max
__device__ __forceinline__ unsigned fkey(float f) {
    unsigned u = __float_as_uint(f);
    return (u & 0x80000000u) ? ~u : (u | 0x80000000u);
}
__device__ __forceinline__ float funkey(unsigned k) {
    return (k & 0x80000000u) ? __uint_as_float(k & 0x7fffffffu)
                             : __uint_as_float(~k);
}

// ---------------- PTX helpers (sm_100-safe: cp.async / ldmatrix / mma.sync) ----
__device__ __forceinline__ unsigned smem_u32(const void* p) {
    return (unsigned)__cvta_generic_to_shared(p);
}
__device__ __forceinline__ void cp16(unsigned dst, const void* src) {
    asm volatile("cp.async.cg.shared.global [%0], [%1], 16;\n" :: "r"(dst), "l"(src));
}
__device__ __forceinline__ void cp_commit() { asm volatile("cp.async.commit_group;\n" ::); }
__device__ __forceinline__ void cp_wait2()  { asm volatile("cp.async.wait_group 2;\n" ::); }
__device__ __forceinline__ void ldsm_x4(unsigned* r, unsigned addr) {
    asm volatile("ldmatrix.sync.aligned.m8n8.x4.shared.b16 {%0,%1,%2,%3},[%4];"
                 : "=r"(r[0]), "=r"(r[1]), "=r"(r[2]), "=r"(r[3]) : "r"(addr));
}
__device__ __forceinline__ void ldsm_x4_t(unsigned* r, unsigned addr) {
    asm volatile("ldmatrix.sync.aligned.m8n8.x4.trans.shared.b16 {%0,%1,%2,%3},[%4];"
                 : "=r"(r[0]), "=r"(r[1]), "=r"(r[2]), "=r"(r[3]) : "r"(addr));
}
__device__ __forceinline__ void mma16816(float* d, const unsigned* a, unsigned b0, unsigned b1) {
    asm volatile("mma.sync.aligned.m16n8k16.row.col.f32.f16.f16.f32 "
                 "{%0,%1,%2,%3},{%4,%5,%6,%7},{%8,%9},{%0,%1,%2,%3};"
                 : "+f"(d[0]), "+f"(d[1]), "+f"(d[2]), "+f"(d[3])
                 : "r"(a[0]), "r"(a[1]), "r"(a[2]), "r"(a[3]), "r"(b0), "r"(b1));
}

// ---------------- K0: offsets + pool init ----------------
__global__ void k_init(const int* npts, int B) {
    int tid = blockIdx.x * blockDim.x + threadIdx.x;
    if (blockIdx.x == 0 && threadIdx.x == 0) {
        int acc = 0; g_off[0] = 0;
        for (int b = 0; b < B; b++) { acc += npts[b]; g_off[b + 1] = acc; }
    }
    int stride = gridDim.x * blockDim.x;
    for (int i = tid; i < MAXB * 256;  i += stride) g_pool1u[i] = 0u;
    for (int i = tid; i < MAXB * 1024; i += stride) g_pool2u[i] = 0u;
}

__global__ void k_segid(int N, int B) {
    int n = blockIdx.x * blockDim.x + threadIdx.x;
    if (n >= N) return;
    int s = 0;
    while (s + 1 < B && g_off[s + 1] <= n) s++;
    g_segid[n] = (unsigned char)s;
}

__global__ void k_convW(const float* __restrict__ W2a, const float* __restrict__ W2b) {
    int i = blockIdx.x * blockDim.x + threadIdx.x;
    if (i < 512 * 512)  g_W2a_h[i] = __float2half_rn(W2a[i]);
    if (i < 1024 * 512) g_W2b_h[i] = __float2half_rn(W2b[i]);
}

// ---------------- K1a: x moments ----------------
__global__ void k_xstats(const float* __restrict__ x, int N) {
    float s0 = 0, s1 = 0, s2 = 0, q0 = 0, q1 = 0, q2 = 0, q3 = 0, q4 = 0, q5 = 0;
    int stride = gridDim.x * blockDim.x;
    for (int n = blockIdx.x * blockDim.x + threadIdx.x; n < N; n += stride) {
        float a = x[n], b = x[N + n], c = x[2 * N + n];
        s0 += a; s1 += b; s2 += c;
        q0 += a * a; q1 += a * b; q2 += a * c; q3 += b * b; q4 += b * c; q5 += c * c;
    }
    __shared__ float rb[256];
    float vals[9] = {s0, s1, s2, q0, q1, q2, q3, q4, q5};
    for (int v = 0; v < 9; v++) {
        rb[threadIdx.x] = vals[v];
        __syncthreads();
        for (int st = 128; st > 0; st >>= 1) {
            if (threadIdx.x < st) rb[threadIdx.x] += rb[threadIdx.x + st];
            __syncthreads();
        }
        if (threadIdx.x == 0) g_xpart[blockIdx.x * 9 + v] = rb[0];
        __syncthreads();
    }
}

// ---------------- K1b: fold BN1 into conv1a ----------------
__global__ void k_fold1(const float* __restrict__ W1a, const float* __restrict__ b1a,
                        const float* __restrict__ g1,  const float* __restrict__ be1,
                        int N, int nblocks) {
    __shared__ double S[9];
    __shared__ float mu[3], C[3][3];
    if (threadIdx.x < 9) {
        double a = 0;
        for (int b = 0; b < nblocks; b++) a += (double)g_xpart[b * 9 + threadIdx.x];
        S[threadIdx.x] = a;
    }
    __syncthreads();
    if (threadIdx.x == 0) {
        double invN = 1.0 / (double)N;
        double m0 = S[0] * invN, m1 = S[1] * invN, m2 = S[2] * invN;
        mu[0] = (float)m0; mu[1] = (float)m1; mu[2] = (float)m2;
        C[0][0] = (float)(S[3] * invN - m0 * m0);
        C[0][1] = (float)(S[4] * invN - m0 * m1);
        C[0][2] = (float)(S[5] * invN - m0 * m2);
        C[1][1] = (float)(S[6] * invN - m1 * m1);
        C[1][2] = (float)(S[7] * invN - m1 * m2);
        C[2][2] = (float)(S[8] * invN - m2 * m2);
        C[1][0] = C[0][1]; C[2][0] = C[0][2]; C[2][1] = C[1][2];
    }
    __syncthreads();
    int c = threadIdx.x;
    float w0 = W1a[c * 3], w1 = W1a[c * 3 + 1], w2 = W1a[c * 3 + 2];
    float mean1 = w0 * mu[0] + w1 * mu[1] + w2 * mu[2] + b1a[c];
    float var1 = w0 * w0 * C[0][0] + w1 * w1 * C[1][1] + w2 * w2 * C[2][2]
               + 2.f * (w0 * w1 * C[0][1] + w0 * w2 * C[0][2] + w1 * w2 * C[1][2]);
    float a = g1[c] * rsqrtf(var1 + EPSV);
    g_Wf1[c * 3 + 0] = a * w0;
    g_Wf1[c * 3 + 1] = a * w1;
    g_Wf1[c * 3 + 2] = a * w2;
    g_bf1[c] = a * (b1a[c] - mean1) + be1[c];
}

// ---------------- K2: fused conv1a+BN1+ReLU+conv1b + seg-max(pool1) ----------------
__global__ void __launch_bounds__(256) k_stage1(const float* __restrict__ x,
                                                const float* __restrict__ W1b,
                                                const float* __restrict__ b1b,
                                                int N, int B) {
    __shared__ float xs[3 * 64];
    __shared__ float hs[128 * 64];
    __shared__ int s_segA, s_bnd;
    int tid = threadIdx.x;
    int n0 = blockIdx.x * 64;
    if (tid < 192) xs[tid] = x[(tid >> 6) * N + n0 + (tid & 63)];
    if (tid == 0) {
        int s = 0;
        while (s + 1 < B && g_off[s + 1] <= n0) s++;
        s_segA = s; s_bnd = g_off[s + 1];
    }
    __syncthreads();
    #pragma unroll
    for (int i = 0; i < 32; i++) {
        int e = tid + i * 256;
        int c = e >> 6, p = e & 63;
        float h = g_bf1[c] + g_Wf1[c * 3] * xs[p]
                + g_Wf1[c * 3 + 1] * xs[64 + p]
                + g_Wf1[c * 3 + 2] * xs[128 + p];
        hs[e] = fmaxf(h, 0.f);
    }
    __syncthreads();
    float acc[64];
    #pragma unroll
    for (int p = 0; p < 64; p++) acc[p] = 0.f;
    const float* wrow = W1b + tid * 128;
    for (int k0 = 0; k0 < 128; k0 += 16) {
        float4 w4[4];
        w4[0] = *(const float4*)(wrow + k0);
        w4[1] = *(const float4*)(wrow + k0 + 4);
        w4[2] = *(const float4*)(wrow + k0 + 8);
        w4[3] = *(const float4*)(wrow + k0 + 12);
        const float* wv = (const float*)w4;
        #pragma unroll
        for (int kk = 0; kk < 16; kk++) {
            float w = wv[kk];
            const float4* hp = (const float4*)&hs[(k0 + kk) * 64];
            #pragma unroll
            for (int p4 = 0; p4 < 16; p4++) {
                float4 hv = hp[p4];
                acc[p4 * 4 + 0] += w * hv.x;
                acc[p4 * 4 + 1] += w * hv.y;
                acc[p4 * 4 + 2] += w * hv.z;
                acc[p4 * 4 + 3] += w * hv.w;
            }
        }
    }
    float bb = b1b[tid];
    float mA = -CUDART_INF_F, mB = -CUDART_INF_F;
    int bnd = s_bnd;
    __half* dst = &g_mlph[(size_t)tid * N + n0];
    #pragma unroll
    for (int p = 0; p < 64; p++) {
        float v = acc[p] + bb;
        acc[p] = v;
        if (n0 + p < bnd) mA = fmaxf(mA, v); else mB = fmaxf(mB, v);
    }
    #pragma unroll
    for (int p2 = 0; p2 < 32; p2++) {
        *(__half2*)&dst[p2 * 2] = __floats2half2_rn(acc[2 * p2], acc[2 * p2 + 1]);
    }
    atomicMax(&g_pool1u[s_segA * 256 + tid], fkey(mA));
    if (bnd < n0 + 64) atomicMax(&g_pool1u[(s_segA + 1) * 256 + tid], fkey(mB));
}

__global__ void k_decode1(int B) {
    int i = blockIdx.x * blockDim.x + threadIdx.x;
    if (i < B * 256) g_pool1h[i] = __float2half_rn(funkey(g_pool1u[i]));
}

// ---------------- broadcast sym into g_symh [c][N] ----------------
__global__ void k_bcast(int N) {
    int c = blockIdx.y;
    int n0 = (blockIdx.x * blockDim.x + threadIdx.x) * 8;
    if (n0 >= N) return;
    union { uint2 u; unsigned char b[8]; } sg;
    sg.u = *(const uint2*)&g_segid[n0];
    union { uint4 u; __half h[8]; } o;
    #pragma unroll
    for (int j = 0; j < 8; j++) o.h[j] = g_pool1h[sg.b[j] * 256 + c];
    *(uint4*)&g_symh[(size_t)c * N + n0] = o.u;
}

// ---------------- tensor-core GEMMs (legacy mma.sync, 3-stage cp.async) -------
// Block tile: 128 channels (c0) x 256 points (n0), K-step 16, 256 threads,
// 8 warps of 64x64. MODE 0: B=[mlp;sym], write y2 + BN2 stat partials.
// MODE 1: B=activated y2, fused segment-max epilogue.
template<int MODE>
__global__ void __launch_bounds__(256) k_mma(const float* __restrict__ bias,
                                             int N, int B) {
    __shared__ __align__(16) __half As[3][128][24];
    __shared__ __align__(16) __half Bs[3][16][264];
    __shared__ float s_red[128][4];
    __shared__ int s_seg, s_bnd;

    const int tid = threadIdx.x, lane = tid & 31, wid = tid >> 5;
    const int wm = wid & 1, wn = wid >> 1;
    const int quad = lane >> 2, qlane = lane & 3;
    const int n0 = blockIdx.x * 256;
    const int c0 = blockIdx.y * 128;

    const __half* __restrict__ Aw = (MODE == 0 ? g_W2a_h : g_W2b_h);
    const int KSTEPS = 32;  // K = 512

    if (MODE == 1 && tid == 0) {
        int s = g_segid[n0];
        s_seg = s; s_bnd = g_off[s + 1];
    }

    // ldmatrix smem addresses for the 3 buffers
    unsigned aAddr[3][4], bAddr[3][4];
    #pragma unroll
    for (int s = 0; s < 3; s++) {
        unsigned aBase = smem_u32(&As[s][0][0]);
        unsigned bBase = smem_u32(&Bs[s][0][0]);
        #pragma unroll
        for (int mf = 0; mf < 4; mf++)
            aAddr[s][mf] = aBase + (((wm * 64 + mf * 16 + (lane & 15)) * 24
                                     + (lane >> 4) * 8) << 1);
        #pragma unroll
        for (int np = 0; np < 4; np++)
            bAddr[s][np] = bBase + (((lane & 15) * 264 + wn * 64 + np * 16
                                     + (lane >> 4) * 8) << 1);
    }

    float acc[4][8][4];
    #pragma unroll
    for (int m = 0; m < 4; m++)
        #pragma unroll
        for (int n = 0; n < 8; n++)
            #pragma unroll
            for (int v = 0; v < 4; v++) acc[m][n][v] = 0.f;

    auto issueLoad = [&](int ks, int s) {
        {   // A tile: 128 rows x 16 k, one 16B chunk per thread
            int row = tid >> 1, c8 = (tid & 1) * 8;
            cp16(smem_u32(&As[s][row][c8]),
                 Aw + (size_t)(c0 + row) * 512 + ks * 16 + c8);
        }
        #pragma unroll
        for (int i = 0; i < 2; i++) {  // B tile: 16 rows x 256 n, 2 chunks/thread
            int q = tid + i * 256;
            int row = q >> 5, col8 = (q & 31) * 8;
            int kg = ks * 16 + row;
            const __half* src;
            if (MODE == 0)
                src = (kg < 256) ? (g_mlph + (size_t)kg * N)
                                 : (g_symh + (size_t)(kg - 256) * N);
            else
                src = g_y2h + (size_t)kg * N;
            cp16(smem_u32(&Bs[s][row][col8]), src + n0 + col8);
        }
    };

    issueLoad(0, 0); cp_commit();
    issueLoad(1, 1); cp_commit();

    int buf = 0;
    for (int ks = 0; ks < KSTEPS; ks++) {
        if (ks + 2 < KSTEPS) issueLoad(ks + 2, (ks + 2) % 3);
        cp_commit();
        cp_wait2();
        __syncthreads();
        unsigned af[4][4], bf[4][4];
        #pragma unroll
        for (int mf = 0; mf < 4; mf++) ldsm_x4(af[mf], aAddr[buf][mf]);
        #pragma unroll
        for (int np = 0; np < 4; np++) ldsm_x4_t(bf[np], bAddr[buf][np]);
        #pragma unroll
        for (int mf = 0; mf < 4; mf++)
            #pragma unroll
            for (int nf = 0; nf < 8; nf++)
                mma16816(acc[mf][nf], af[mf], bf[nf >> 1][(nf & 1) * 2],
                         bf[nf >> 1][(nf & 1) * 2 + 1]);
        __syncthreads();
        buf = (buf == 2) ? 0 : buf + 1;
    }

    // ---------------- epilogues ----------------
    if (MODE == 0) {
        int nb = blockIdx.x;
        float sums[4][2], sqs[4][2];
        #pragma unroll
        for (int mf = 0; mf < 4; mf++) {
            int cA = c0 + wm * 64 + mf * 16 + quad;
            int cB = cA + 8;
            float bA = bias[cA], bB = bias[cB];
            float sA = 0, qA = 0, sB = 0, qB = 0;
            #pragma unroll
            for (int nf = 0; nf < 8; nf++) {
                int n = n0 + wn * 64 + nf * 8 + qlane * 2;
                float v0 = acc[mf][nf][0] + bA;
                float v1 = acc[mf][nf][1] + bA;
                float v2 = acc[mf][nf][2] + bB;
                float v3 = acc[mf][nf][3] + bB;
                *(__half2*)&g_y2h[(size_t)cA * N + n] = __floats2half2_rn(v0, v1);
                *(__half2*)&g_y2h[(size_t)cB * N + n] = __floats2half2_rn(v2, v3);
                sA += v0 + v1; qA += v0 * v0 + v1 * v1;
                sB += v2 + v3; qB += v2 * v2 + v3 * v3;
            }
            sums[mf][0] = sA; sums[mf][1] = sB;
            sqs[mf][0] = qA;  sqs[mf][1] = qB;
        }
        #pragma unroll
        for (int mf = 0; mf < 4; mf++)
            #pragma unroll
            for (int h = 0; h < 2; h++) {
                float v = sums[mf][h];
                v += __shfl_xor_sync(0xffffffff, v, 1);
                v += __shfl_xor_sync(0xffffffff, v, 2);
                if (qlane == 0) s_red[wm * 64 + mf * 16 + h * 8 + quad][wn] = v;
            }
        __syncthreads();
        if (tid < 128)
            g_psum[(size_t)(c0 + tid) * 512 + nb] =
                s_red[tid][0] + s_red[tid][1] + s_red[tid][2] + s_red[tid][3];
        __syncthreads();
        #pragma unroll
        for (int mf = 0; mf < 4; mf++)
            #pragma unroll
            for (int h = 0; h < 2; h++) {
                float v = sqs[mf][h];
                v += __shfl_xor_sync(0xffffffff, v, 1);
                v += __shfl_xor_sync(0xffffffff, v, 2);
                if (qlane == 0) s_red[wm * 64 + mf * 16 + h * 8 + quad][wn] = v;
            }
        __syncthreads();
        if (tid < 128)
            g_psq[(size_t)(c0 + tid) * 512 + nb] =
                s_red[tid][0] + s_red[tid][1] + s_red[tid][2] + s_red[tid][3];
    } else {
        __syncthreads();
        int bnd = s_bnd;
        bool hasB = (bnd < n0 + 256);
        float mA[4][2], mB[4][2];
        #pragma unroll
        for (int mf = 0; mf < 4; mf++) {
            int cA = c0 + wm * 64 + mf * 16 + quad;
            float bA = bias[cA], bB = bias[cA + 8];
            float a0 = -CUDART_INF_F, b0 = -CUDART_INF_F;
            float a1 = -CUDART_INF_F, b1 = -CUDART_INF_F;
            #pragma unroll
            for (int nf = 0; nf < 8; nf++) {
                int n = n0 + wn * 64 + nf * 8 + qlane * 2;
                float v0 = acc[mf][nf][0] + bA;
                float v1 = acc[mf][nf][1] + bA;
                float v2 = acc[mf][nf][2] + bB;
                float v3 = acc[mf][nf][3] + bB;
                if (n < bnd)     a0 = fmaxf(a0, v0); else b0 = fmaxf(b0, v0);
                if (n + 1 < bnd) a0 = fmaxf(a0, v1); else b0 = fmaxf(b0, v1);
                if (n < bnd)     a1 = fmaxf(a1, v2); else b1 = fmaxf(b1, v2);
                if (n + 1 < bnd) a1 = fmaxf(a1, v3); else b1 = fmaxf(b1, v3);
            }
            mA[mf][0] = a0; mA[mf][1] = a1;
            mB[mf][0] = b0; mB[mf][1] = b1;
        }
        #pragma unroll
        for (int mf = 0; mf < 4; mf++)
            #pragma unroll
            for (int h = 0; h < 2; h++) {
                float v = mA[mf][h];
                v = fmaxf(v, __shfl_xor_sync(0xffffffff, v, 1));
                v = fmaxf(v, __shfl_xor_sync(0xffffffff, v, 2));
                if (qlane == 0) s_red[wm * 64 + mf * 16 + h * 8 + quad][wn] = v;
            }
        __syncthreads();
        if (tid < 128) {
            float m = fmaxf(fmaxf(s_red[tid][0], s_red[tid][1]),
                            fmaxf(s_red[tid][2], s_red[tid][3]));
            atomicMax(&g_pool2u[s_seg * 1024 + c0 + tid], fkey(m));
        }
        __syncthreads();
        if (hasB) {
            #pragma unroll
            for (int mf = 0; mf < 4; mf++)
                #pragma unroll
                for (int h = 0; h < 2; h++) {
                    float v = mB[mf][h];
                    v = fmaxf(v, __shfl_xor_sync(0xffffffff, v, 1));
                    v = fmaxf(v, __shfl_xor_sync(0xffffffff, v, 2));
                    if (qlane == 0) s_red[wm * 64 + mf * 16 + h * 8 + quad][wn] = v;
                }
            __syncthreads();
            if (tid < 128) {
                float m = fmaxf(fmaxf(s_red[tid][0], s_red[tid][1]),
                                fmaxf(s_red[tid][2], s_red[tid][3]));
                atomicMax(&g_pool2u[(s_seg + 1) * 1024 + c0 + tid], fkey(m));
            }
        }
    }
}

// ---------------- K4: reduce BN2 stats ----------------
__global__ void k_bn2(const float* __restrict__ g2, const float* __restrict__ be2,
                      int N, int NB) {
    int c = blockIdx.x * blockDim.x + threadIdx.x;
    if (c >= 512) return;
    double s = 0, q = 0;
    for (int nb = 0; nb < NB; nb++) {
        s += (double)g_psum[(size_t)c * 512 + nb];
        q += (double)g_psq [(size_t)c * 512 + nb];
    }
    double mean = s / (double)N;
    double var  = q / (double)N - mean * mean;
    float a = g2[c] * rsqrtf((float)var + EPSV);
    g_a2[c] = a;
    g_c2[c] = be2[c] - (float)mean * a;
}

// ---------------- K5: in-place activation z = relu(a2*y2 + c2) ----------------
__global__ void k_act(int N) {
    int c = blockIdx.y;
    size_t base = (size_t)c * N + (size_t)(blockIdx.x * blockDim.x + threadIdx.x) * 8;
    float a = g_a2[c], cc = g_c2[c];
    union { uint4 u; __half h[8]; } v;
    v.u = *(const uint4*)&g_y2h[base];
    #pragma unroll
    for (int j = 0; j < 8; j++)
        v.h[j] = __float2half_rn(fmaxf(fmaf(a, __half2float(v.h[j]), cc), 0.f));
    *(uint4*)&g_y2h[base] = v.u;
}

// ---------------- K6: decode output ----------------
__global__ void k_out(float* __restrict__ out, int B) {
    int i = blockIdx.x * blockDim.x + threadIdx.x;
    if (i < B * 1024) out[i] = funkey(g_pool2u[i]);
}

// ---------------- launch ----------------
extern "C" void kernel_launch(void* const* d_in, const int* in_sizes, int n_in,
                              void* d_out, int out_size) {
    const float* x   = (const float*)d_in[0];
    const int*   np  = (const int*)  d_in[1];
    const float* W1a = (const float*)d_in[2];
    const float* b1a = (const float*)d_in[3];
    const float* g1  = (const float*)d_in[4];
    const float* be1 = (const float*)d_in[5];
    const float* W1b = (const float*)d_in[6];
    const float* b1b = (const float*)d_in[7];
    const float* W2a = (const float*)d_in[8];
    const float* b2a = (const float*)d_in[9];
    const float* g2  = (const float*)d_in[10];
    const float* be2 = (const float*)d_in[11];
    const float* W2b = (const float*)d_in[12];
    const float* b2b = (const float*)d_in[13];
    int N = in_sizes[0] / 3;
    int B = in_sizes[1];
    if (N > MAXN) N = MAXN;

    k_init<<<32, 256>>>(np, B);
    k_segid<<<(N + 255) / 256, 256>>>(N, B);
    k_convW<<<2048, 256>>>(W2a, W2b);
    k_xstats<<<128, 256>>>(x, N);
    k_fold1<<<1, 128>>>(W1a, b1a, g1, be1, N, 128);
    k_stage1<<<N / 64, 256>>>(x, W1b, b1b, N, B);
    k_decode1<<<(B * 256 + 255) / 256, 256>>>(B);
    dim3 gb(N / 2048, 256);
    k_bcast<<<gb, 256>>>(N);
    dim3 g3(N / 256, 4);
    k_mma<0><<<g3, 256>>>(b2a, N, B);
    k_bn2<<<2, 256>>>(g2, be2, N, N / 256);
    dim3 ga(N / 2048, 512);
    k_act<<<ga, 256>>>(N);
    dim3 g5(N / 256, 8);
    k_mma<1><<<g5, 256>>>(b2b, N, B);
    k_out<<<(B * 1024 + 255) / 256, 256>>>((float*)d_out, B);
}

// round 9
// speedup vs baseline: 2.0150x; 1.5010x over previous
#include <cuda_runtime.h>
#include <cuda_fp16.h>
#include <math_constants.h>
#include <cstdint>

#define MAXN 131072
#define MAXB 32
#define EPSV 1e-5f

// ---------------- scratch (static device globals; no allocation) ----------------
__device__ __align__(16) __half g_mlph[256 * MAXN];   // mlp_feat fp16 [c][N] (64 MB)
__device__ __align__(16) __half g_y2h [512 * MAXN];   // y2 fp16 [c][N]; activated in-place
__device__ __align__(16) __half g_W2a_h[512 * 512];
__device__ __align__(16) __half g_W2b_h[1024 * 512];
__device__ __align__(16) __half g_W1b_h[256 * 128];
__device__ float    g_psum[512 * 1024];
__device__ float    g_psq [512 * 1024];
__device__ float    g_xpart[128 * 9];
__device__ float    g_Wf1[128 * 3];
__device__ float    g_bf1[128];
__device__ float    g_a2[512];
__device__ float    g_c2[512];
__device__ unsigned g_pool1u[MAXB * 256];
__device__ float    g_pool1f[MAXB * 256];
__device__ float    g_ysym[MAXB * 512];    // [seg][c] fp32 sym contribution
__device__ unsigned g_pool2u[MAXB * 1024];
__device__ int      g_off[MAXB + 1];
__device__ __align__(8) unsigned char g_segid[MAXN];

// monotonic float<->uint key for exact atomic max
__device__ __forceinline__ unsigned fkey(float f) {
    unsigned u = __float_as_uint(f);
    return (u & 0x80000000u) ? ~u : (u | 0x80000000u);
}
__device__ __forceinline__ float funkey(unsigned k) {
    return (k & 0x80000000u) ? __uint_as_float(k & 0x7fffffffu)
                             : __uint_as_float(~k);
}

// ---------------- PTX helpers ----------------
__device__ __forceinline__ unsigned smem_u32(const void* p) {
    return (unsigned)__cvta_generic_to_shared(p);
}
__device__ __forceinline__ void cp16(unsigned dst, const void* src) {
    asm volatile("cp.async.cg.shared.global [%0], [%1], 16;\n" :: "r"(dst), "l"(src));
}
__device__ __forceinline__ void cp_commit() { asm volatile("cp.async.commit_group;\n" ::); }
__device__ __forceinline__ void cp_wait0()  { asm volatile("cp.async.wait_group 0;\n" ::); }
__device__ __forceinline__ void cp_wait2()  { asm volatile("cp.async.wait_group 2;\n" ::); }
__device__ __forceinline__ void ldsm_x4(unsigned* r, unsigned addr) {
    asm volatile("ldmatrix.sync.aligned.m8n8.x4.shared.b16 {%0,%1,%2,%3},[%4];"
                 : "=r"(r[0]), "=r"(r[1]), "=r"(r[2]), "=r"(r[3]) : "r"(addr));
}
__device__ __forceinline__ void ldsm_x4_t(unsigned* r, unsigned addr) {
    asm volatile("ldmatrix.sync.aligned.m8n8.x4.trans.shared.b16 {%0,%1,%2,%3},[%4];"
                 : "=r"(r[0]), "=r"(r[1]), "=r"(r[2]), "=r"(r[3]) : "r"(addr));
}
__device__ __forceinline__ void mma16816(float* d, const unsigned* a, unsigned b0, unsigned b1) {
    asm volatile("mma.sync.aligned.m16n8k16.row.col.f32.f16.f16.f32 "
                 "{%0,%1,%2,%3},{%4,%5,%6,%7},{%8,%9},{%0,%1,%2,%3};"
                 : "+f"(d[0]), "+f"(d[1]), "+f"(d[2]), "+f"(d[3])
                 : "r"(a[0]), "r"(a[1]), "r"(a[2]), "r"(a[3]), "r"(b0), "r"(b1));
}

// ---------------- K0: offsets + pool init ----------------
__global__ void k_init(const int* npts, int B) {
    int tid = blockIdx.x * blockDim.x + threadIdx.x;
    if (blockIdx.x == 0 && threadIdx.x == 0) {
        int acc = 0; g_off[0] = 0;
        for (int b = 0; b < B; b++) { acc += npts[b]; g_off[b + 1] = acc; }
    }
    int stride = gridDim.x * blockDim.x;
    for (int i = tid; i < MAXB * 256;  i += stride) g_pool1u[i] = 0u;
    for (int i = tid; i < MAXB * 1024; i += stride) g_pool2u[i] = 0u;
}

__global__ void k_segid(int N, int B) {
    int n = blockIdx.x * blockDim.x + threadIdx.x;
    if (n >= N) return;
    int s = 0;
    while (s + 1 < B && g_off[s + 1] <= n) s++;
    g_segid[n] = (unsigned char)s;
}

__global__ void k_convW(const float* __restrict__ W2a, const float* __restrict__ W2b,
                        const float* __restrict__ W1b) {
    int i = blockIdx.x * blockDim.x + threadIdx.x;
    if (i < 512 * 512)  g_W2a_h[i] = __float2half_rn(W2a[i]);
    if (i < 1024 * 512) g_W2b_h[i] = __float2half_rn(W2b[i]);
    if (i < 256 * 128)  g_W1b_h[i] = __float2half_rn(W1b[i]);
}

// ---------------- K1a: x moments ----------------
__global__ void k_xstats(const float* __restrict__ x, int N) {
    float s0 = 0, s1 = 0, s2 = 0, q0 = 0, q1 = 0, q2 = 0, q3 = 0, q4 = 0, q5 = 0;
    int stride = gridDim.x * blockDim.x;
    for (int n = blockIdx.x * blockDim.x + threadIdx.x; n < N; n += stride) {
        float a = x[n], b = x[N + n], c = x[2 * N + n];
        s0 += a; s1 += b; s2 += c;
        q0 += a * a; q1 += a * b; q2 += a * c; q3 += b * b; q4 += b * c; q5 += c * c;
    }
    __shared__ float rb[256];
    float vals[9] = {s0, s1, s2, q0, q1, q2, q3, q4, q5};
    for (int v = 0; v < 9; v++) {
        rb[threadIdx.x] = vals[v];
        __syncthreads();
        for (int st = 128; st > 0; st >>= 1) {
            if (threadIdx.x < st) rb[threadIdx.x] += rb[threadIdx.x + st];
            __syncthreads();
        }
        if (threadIdx.x == 0) g_xpart[blockIdx.x * 9 + v] = rb[0];
        __syncthreads();
    }
}

// ---------------- K1b: fold BN1 into conv1a ----------------
__global__ void k_fold1(const float* __restrict__ W1a, const float* __restrict__ b1a,
                        const float* __restrict__ g1,  const float* __restrict__ be1,
                        int N, int nblocks) {
    __shared__ double S[9];
    __shared__ float mu[3], C[3][3];
    if (threadIdx.x < 9) {
        double a = 0;
        for (int b = 0; b < nblocks; b++) a += (double)g_xpart[b * 9 + threadIdx.x];
        S[threadIdx.x] = a;
    }
    __syncthreads();
    if (threadIdx.x == 0) {
        double invN = 1.0 / (double)N;
        double m0 = S[0] * invN, m1 = S[1] * invN, m2 = S[2] * invN;
        mu[0] = (float)m0; mu[1] = (float)m1; mu[2] = (float)m2;
        C[0][0] = (float)(S[3] * invN - m0 * m0);
        C[0][1] = (float)(S[4] * invN - m0 * m1);
        C[0][2] = (float)(S[5] * invN - m0 * m2);
        C[1][1] = (float)(S[6] * invN - m1 * m1);
        C[1][2] = (float)(S[7] * invN - m1 * m2);
        C[2][2] = (float)(S[8] * invN - m2 * m2);
        C[1][0] = C[0][1]; C[2][0] = C[0][2]; C[2][1] = C[1][2];
    }
    __syncthreads();
    int c = threadIdx.x;
    float w0 = W1a[c * 3], w1 = W1a[c * 3 + 1], w2 = W1a[c * 3 + 2];
    float mean1 = w0 * mu[0] + w1 * mu[1] + w2 * mu[2] + b1a[c];
    float var1 = w0 * w0 * C[0][0] + w1 * w1 * C[1][1] + w2 * w2 * C[2][2]
               + 2.f * (w0 * w1 * C[0][1] + w0 * w2 * C[0][2] + w1 * w2 * C[1][2]);
    float a = g1[c] * rsqrtf(var1 + EPSV);
    g_Wf1[c * 3 + 0] = a * w0;
    g_Wf1[c * 3 + 1] = a * w1;
    g_Wf1[c * 3 + 2] = a * w2;
    g_bf1[c] = a * (b1a[c] - mean1) + be1[c];
}

// ---------------- K2: stage1 via tensor cores -------------------------------
// Block = 128 points. Conv 3->128 (folded BN+ReLU) into smem fp16, then
// mma.sync 256x128x128 with W1b resident in smem. Fused pool1 seg-max.
#define S1_SMEM ((256 + 128) * 136 * 2)
__global__ void __launch_bounds__(256) k_stage1_tc(const float* __restrict__ x,
                                                   const float* __restrict__ b1b,
                                                   int N, int B) {
    extern __shared__ __align__(16) char dyn1[];
    __half* Ws = (__half*)dyn1;                       // [256][136]
    __half* Hs = (__half*)(dyn1 + 256 * 136 * 2);     // [128][136]
    __shared__ float xs[3][128];
    __shared__ float s_redA[256][2], s_redB[256][2];
    __shared__ int s_seg, s_bnd;

    const int tid = threadIdx.x, lane = tid & 31, wid = tid >> 5;
    const int wm = wid & 3, wn = wid >> 2;       // 4x2 warps: 256 ch x 128 pts
    const int quad = lane >> 2, qlane = lane & 3;
    const int n0 = blockIdx.x * 128;

    // stream W1b fp16 into padded smem
    #pragma unroll
    for (int i = 0; i < 16; i++) {
        int q = tid + i * 256;
        int r = q >> 4, c8 = (q & 15) * 8;
        cp16(smem_u32(&Ws[r * 136 + c8]), g_W1b_h + r * 128 + c8);
    }
    cp_commit();
    if (tid < 128) {
        xs[0][tid] = x[n0 + tid];
        xs[1][tid] = x[N + n0 + tid];
        xs[2][tid] = x[2 * N + n0 + tid];
    }
    if (tid == 0) {
        int s = g_segid[n0];
        s_seg = s; s_bnd = g_off[s + 1];
    }
    __syncthreads();

    // conv: thread t -> channel t>>1, 64 points
    {
        int c = tid >> 1, p0 = (tid & 1) * 64;
        float w0 = g_Wf1[c * 3], w1 = g_Wf1[c * 3 + 1], w2 = g_Wf1[c * 3 + 2];
        float b = g_bf1[c];
        #pragma unroll
        for (int j = 0; j < 64; j += 2) {
            int p = p0 + j;
            float h0 = fmaxf(b + w0 * xs[0][p]   + w1 * xs[1][p]   + w2 * xs[2][p],   0.f);
            float h1 = fmaxf(b + w0 * xs[0][p+1] + w1 * xs[1][p+1] + w2 * xs[2][p+1], 0.f);
            *(__half2*)&Hs[c * 136 + p] = __floats2half2_rn(h0, h1);
        }
    }
    cp_wait0();
    __syncthreads();

    float acc[4][8][4];
    #pragma unroll
    for (int m = 0; m < 4; m++)
        #pragma unroll
        for (int n = 0; n < 8; n++)
            #pragma unroll
            for (int v = 0; v < 4; v++) acc[m][n][v] = 0.f;

    unsigned aBase = smem_u32(Ws), bBase = smem_u32(Hs);
    unsigned aA0[4], bA0[4];
    #pragma unroll
    for (int mf = 0; mf < 4; mf++)
        aA0[mf] = aBase + (((wm * 64 + mf * 16 + (lane & 15)) * 136
                            + (lane >> 4) * 8) << 1);
    #pragma unroll
    for (int np = 0; np < 4; np++)
        bA0[np] = bBase + (((lane & 15) * 136 + wn * 64 + np * 16
                            + (lane >> 4) * 8) << 1);

    #pragma unroll
    for (int ks = 0; ks < 8; ks++) {
        unsigned af[4][4], bf[4][4];
        #pragma unroll
        for (int mf = 0; mf < 4; mf++) ldsm_x4(af[mf], aA0[mf] + ks * 32);
        #pragma unroll
        for (int np = 0; np < 4; np++) ldsm_x4_t(bf[np], bA0[np] + ks * 16 * 272);
        #pragma unroll
        for (int mf = 0; mf < 4; mf++)
            #pragma unroll
            for (int nf = 0; nf < 8; nf++)
                mma16816(acc[mf][nf], af[mf], bf[nf >> 1][(nf & 1) * 2],
                         bf[nf >> 1][(nf & 1) * 2 + 1]);
    }

    // epilogue: bias, write g_mlph [c][N], fused pool1 seg-max
    int bnd = s_bnd;
    bool hasB = (bnd < n0 + 128);
    #pragma unroll
    for (int mf = 0; mf < 4; mf++) {
        int cA = wm * 64 + mf * 16 + quad;
        int cB = cA + 8;
        float bA = b1b[cA], bB = b1b[cB];
        float a0 = -CUDART_INF_F, b0 = -CUDART_INF_F;
        float a1 = -CUDART_INF_F, b1 = -CUDART_INF_F;
        #pragma unroll
        for (int nf = 0; nf < 8; nf++) {
            int n = n0 + wn * 64 + nf * 8 + qlane * 2;
            float v0 = acc[mf][nf][0] + bA;
            float v1 = acc[mf][nf][1] + bA;
            float v2 = acc[mf][nf][2] + bB;
            float v3 = acc[mf][nf][3] + bB;
            *(__half2*)&g_mlph[(size_t)cA * N + n] = __floats2half2_rn(v0, v1);
            *(__half2*)&g_mlph[(size_t)cB * N + n] = __floats2half2_rn(v2, v3);
            if (n < bnd)     a0 = fmaxf(a0, v0); else b0 = fmaxf(b0, v0);
            if (n + 1 < bnd) a0 = fmaxf(a0, v1); else b0 = fmaxf(b0, v1);
            if (n < bnd)     a1 = fmaxf(a1, v2); else b1 = fmaxf(b1, v2);
            if (n + 1 < bnd) a1 = fmaxf(a1, v3); else b1 = fmaxf(b1, v3);
        }
        a0 = fmaxf(a0, __shfl_xor_sync(0xffffffff, a0, 1));
        a0 = fmaxf(a0, __shfl_xor_sync(0xffffffff, a0, 2));
        a1 = fmaxf(a1, __shfl_xor_sync(0xffffffff, a1, 1));
        a1 = fmaxf(a1, __shfl_xor_sync(0xffffffff, a1, 2));
        if (qlane == 0) { s_redA[cA][wn] = a0; s_redA[cB][wn] = a1; }
        if (hasB) {
            b0 = fmaxf(b0, __shfl_xor_sync(0xffffffff, b0, 1));
            b0 = fmaxf(b0, __shfl_xor_sync(0xffffffff, b0, 2));
            b1 = fmaxf(b1, __shfl_xor_sync(0xffffffff, b1, 1));
            b1 = fmaxf(b1, __shfl_xor_sync(0xffffffff, b1, 2));
            if (qlane == 0) { s_redB[cA][wn] = b0; s_redB[cB][wn] = b1; }
        }
    }
    __syncthreads();
    if (tid < 256) {
        float m = fmaxf(s_redA[tid][0], s_redA[tid][1]);
        atomicMax(&g_pool1u[s_seg * 256 + tid], fkey(m));
        if (hasB) {
            float mb = fmaxf(s_redB[tid][0], s_redB[tid][1]);
            atomicMax(&g_pool1u[(s_seg + 1) * 256 + tid], fkey(mb));
        }
    }
}

__global__ void k_decode1(int B) {
    int i = blockIdx.x * blockDim.x + threadIdx.x;
    if (i < B * 256) g_pool1f[i] = funkey(g_pool1u[i]);
}

// ---------------- sym fold: ysym[s][c] = W2a[c][256:512] . pool1[s] (fp32) ----
__global__ void k_symfold(const float* __restrict__ W2a, int B) {
    int c = blockIdx.x;           // 0..511
    int tid = threadIdx.x;        // 256
    int s = tid >> 3, kg = tid & 7;
    float acc = 0.f;
    if (s < B) {
        const float* w = W2a + (size_t)c * 512 + 256 + kg * 32;
        const float* p = g_pool1f + s * 256 + kg * 32;
        #pragma unroll
        for (int j = 0; j < 32; j++) acc += w[j] * p[j];
    }
    acc += __shfl_xor_sync(0xffffffff, acc, 1);
    acc += __shfl_xor_sync(0xffffffff, acc, 2);
    acc += __shfl_xor_sync(0xffffffff, acc, 4);
    if (kg == 0 && s < B) g_ysym[s * 512 + c] = acc;
}

// ---------------- tensor-core GEMMs (4-stage cp.async, 1 sync/step) ----------
// MODE 0: K=256, B=g_mlph; epilogue adds bias + ysym[seg], writes y2 + stats.
// MODE 1: K=512, B=activated y2; fused segment-max epilogue.
#define MMA_SMEM ((4 * 128 * 24 + 4 * 16 * 264) * 2)
template<int MODE>
__global__ void __launch_bounds__(256) k_mma(const float* __restrict__ bias,
                                             int N, int B) {
    extern __shared__ __align__(16) char dynm[];
    __half* smemh = (__half*)dynm;
    __shared__ float s_red[128][4];
    __shared__ int s_seg, s_bnd;

    const int tid = threadIdx.x, lane = tid & 31, wid = tid >> 5;
    const int wm = wid & 1, wn = wid >> 1;
    const int quad = lane >> 2, qlane = lane & 3;
    const int n0 = blockIdx.x * 256;
    const int c0 = blockIdx.y * 128;
    const int KSTEPS = (MODE == 0) ? 16 : 32;

    const __half* __restrict__ Aw = (MODE == 0 ? g_W2a_h : g_W2b_h);
    const __half* __restrict__ Bsrc = (MODE == 0 ? g_mlph : g_y2h);

    if (tid == 0) {
        int s = g_segid[n0];
        s_seg = s; s_bnd = g_off[s + 1];
    }

    const unsigned smemBase = smem_u32(smemh);
    // halves offsets: As(s,r,c)=s*3072+r*24+c ; Bs(s,r,c)=12288+s*4224+r*264+c
    auto issueLoad = [&](int ks, int s) {
        {
            int row = tid >> 1, c8 = (tid & 1) * 8;
            cp16(smemBase + ((s * 3072 + row * 24 + c8) << 1),
                 Aw + (size_t)(c0 + row) * 512 + ks * 16 + c8);
        }
        #pragma unroll
        for (int i = 0; i < 2; i++) {
            int q = tid + i * 256;
            int row = q >> 5, col8 = (q & 31) * 8;
            int kg = ks * 16 + row;
            cp16(smemBase + ((12288 + s * 4224 + row * 264 + col8) << 1),
                 Bsrc + (size_t)kg * N + n0 + col8);
        }
    };

    unsigned aA0[4], bA0[4];
    #pragma unroll
    for (int mf = 0; mf < 4; mf++)
        aA0[mf] = smemBase + (((wm * 64 + mf * 16 + (lane & 15)) * 24
                               + (lane >> 4) * 8) << 1);
    #pragma unroll
    for (int np = 0; np < 4; np++)
        bA0[np] = smemBase + ((12288 + (lane & 15) * 264 + wn * 64 + np * 16
                               + (lane >> 4) * 8) << 1);

    float acc[4][8][4];
    #pragma unroll
    for (int m = 0; m < 4; m++)
        #pragma unroll
        for (int n = 0; n < 8; n++)
            #pragma unroll
            for (int v = 0; v < 4; v++) acc[m][n][v] = 0.f;

    issueLoad(0, 0); cp_commit();
    issueLoad(1, 1); cp_commit();
    issueLoad(2, 2); cp_commit();

    for (int ks = 0; ks < KSTEPS; ks++) {
        cp_wait2();
        __syncthreads();
        if (ks + 3 < KSTEPS) issueLoad(ks + 3, (ks + 3) & 3);
        cp_commit();
        int so_a = (ks & 3) * 6144, so_b = (ks & 3) * 8448;
        unsigned af[4][4], bf[4][4];
        #pragma unroll
        for (int mf = 0; mf < 4; mf++) ldsm_x4(af[mf], aA0[mf] + so_a);
        #pragma unroll
        for (int np = 0; np < 4; np++) ldsm_x4_t(bf[np], bA0[np] + so_b);
        #pragma unroll
        for (int mf = 0; mf < 4; mf++)
            #pragma unroll
            for (int nf = 0; nf < 8; nf++)
                mma16816(acc[mf][nf], af[mf], bf[nf >> 1][(nf & 1) * 2],
                         bf[nf >> 1][(nf & 1) * 2 + 1]);
    }
    __syncthreads();

    // ---------------- epilogues ----------------
    int bnd = s_bnd;
    if (MODE == 0) {
        int nb = blockIdx.x;
        int s2 = (s_seg + 1 < B) ? s_seg + 1 : B - 1;
        float sums[4][2], sqs[4][2];
        #pragma unroll
        for (int mf = 0; mf < 4; mf++) {
            int cA = c0 + wm * 64 + mf * 16 + quad;
            int cB = cA + 8;
            float bA = bias[cA], bB = bias[cB];
            float yA1 = g_ysym[s_seg * 512 + cA], yA2 = g_ysym[s2 * 512 + cA];
            float yB1 = g_ysym[s_seg * 512 + cB], yB2 = g_ysym[s2 * 512 + cB];
            float sA = 0, qA = 0, sB = 0, qB = 0;
            #pragma unroll
            for (int nf = 0; nf < 8; nf++) {
                int n = n0 + wn * 64 + nf * 8 + qlane * 2;
                bool i0 = n < bnd, i1 = (n + 1) < bnd;
                float v0 = acc[mf][nf][0] + bA + (i0 ? yA1 : yA2);
                float v1 = acc[mf][nf][1] + bA + (i1 ? yA1 : yA2);
                float v2 = acc[mf][nf][2] + bB + (i0 ? yB1 : yB2);
                float v3 = acc[mf][nf][3] + bB + (i1 ? yB1 : yB2);
                *(__half2*)&g_y2h[(size_t)cA * N + n] = __floats2half2_rn(v0, v1);
                *(__half2*)&g_y2h[(size_t)cB * N + n] = __floats2half2_rn(v2, v3);
                sA += v0 + v1; qA += v0 * v0 + v1 * v1;
                sB += v2 + v3; qB += v2 * v2 + v3 * v3;
            }
            sums[mf][0] = sA; sums[mf][1] = sB;
            sqs[mf][0] = qA;  sqs[mf][1] = qB;
        }
        #pragma unroll
        for (int mf = 0; mf < 4; mf++)
            #pragma unroll
            for (int h = 0; h < 2; h++) {
                float v = sums[mf][h];
                v += __shfl_xor_sync(0xffffffff, v, 1);
                v += __shfl_xor_sync(0xffffffff, v, 2);
                if (qlane == 0) s_red[wm * 64 + mf * 16 + h * 8 + quad][wn] = v;
            }
        __syncthreads();
        if (tid < 128)
            g_psum[(size_t)(c0 + tid) * 512 + nb] =
                s_red[tid][0] + s_red[tid][1] + s_red[tid][2] + s_red[tid][3];
        __syncthreads();
        #pragma unroll
        for (int mf = 0; mf < 4; mf++)
            #pragma unroll
            for (int h = 0; h < 2; h++) {
                float v = sqs[mf][h];
                v += __shfl_xor_sync(0xffffffff, v, 1);
                v += __shfl_xor_sync(0xffffffff, v, 2);
                if (qlane == 0) s_red[wm * 64 + mf * 16 + h * 8 + quad][wn] = v;
            }
        __syncthreads();
        if (tid < 128)
            g_psq[(size_t)(c0 + tid) * 512 + nb] =
                s_red[tid][0] + s_red[tid][1] + s_red[tid][2] + s_red[tid][3];
    } else {
        bool hasB = (bnd < n0 + 256);
        float mA[4][2], mB[4][2];
        #pragma unroll
        for (int mf = 0; mf < 4; mf++) {
            int cA = c0 + wm * 64 + mf * 16 + quad;
            float bA = bias[cA], bB = bias[cA + 8];
            float a0 = -CUDART_INF_F, b0 = -CUDART_INF_F;
            float a1 = -CUDART_INF_F, b1 = -CUDART_INF_F;
            #pragma unroll
            for (int nf = 0; nf < 8; nf++) {
                int n = n0 + wn * 64 + nf * 8 + qlane * 2;
                float v0 = acc[mf][nf][0] + bA;
                float v1 = acc[mf][nf][1] + bA;
                float v2 = acc[mf][nf][2] + bB;
                float v3 = acc[mf][nf][3] + bB;
                if (n < bnd)     a0 = fmaxf(a0, v0); else b0 = fmaxf(b0, v0);
                if (n + 1 < bnd) a0 = fmaxf(a0, v1); else b0 = fmaxf(b0, v1);
                if (n < bnd)     a1 = fmaxf(a1, v2); else b1 = fmaxf(b1, v2);
                if (n + 1 < bnd) a1 = fmaxf(a1, v3); else b1 = fmaxf(b1, v3);
            }
            mA[mf][0] = a0; mA[mf][1] = a1;
            mB[mf][0] = b0; mB[mf][1] = b1;
        }
        #pragma unroll
        for (int mf = 0; mf < 4; mf++)
            #pragma unroll
            for (int h = 0; h < 2; h++) {
                float v = mA[mf][h];
                v = fmaxf(v, __shfl_xor_sync(0xffffffff, v, 1));
                v = fmaxf(v, __shfl_xor_sync(0xffffffff, v, 2));
                if (qlane == 0) s_red[wm * 64 + mf * 16 + h * 8 + quad][wn] = v;
            }
        __syncthreads();
        if (tid < 128) {
            float m = fmaxf(fmaxf(s_red[tid][0], s_red[tid][1]),
                            fmaxf(s_red[tid][2], s_red[tid][3]));
            atomicMax(&g_pool2u[s_seg * 1024 + c0 + tid], fkey(m));
        }
        __syncthreads();
        if (hasB) {
            #pragma unroll
            for (int mf = 0; mf < 4; mf++)
                #pragma unroll
                for (int h = 0; h < 2; h++) {
                    float v = mB[mf][h];
                    v = fmaxf(v, __shfl_xor_sync(0xffffffff, v, 1));
                    v = fmaxf(v, __shfl_xor_sync(0xffffffff, v, 2));
                    if (qlane == 0) s_red[wm * 64 + mf * 16 + h * 8 + quad][wn] = v;
                }
            __syncthreads();
            if (tid < 128) {
                float m = fmaxf(fmaxf(s_red[tid][0], s_red[tid][1]),
                                fmaxf(s_red[tid][2], s_red[tid][3]));
                atomicMax(&g_pool2u[(s_seg + 1) * 1024 + c0 + tid], fkey(m));
            }
        }
    }
}

// ---------------- K4: reduce BN2 stats ----------------
__global__ void k_bn2(const float* __restrict__ g2, const float* __restrict__ be2,
                      int N, int NB) {
    int c = blockIdx.x * blockDim.x + threadIdx.x;
    if (c >= 512) return;
    double s = 0, q = 0;
    for (int nb = 0; nb < NB; nb++) {
        s += (double)g_psum[(size_t)c * 512 + nb];
        q += (double)g_psq [(size_t)c * 512 + nb];
    }
    double mean = s / (double)N;
    double var  = q / (double)N - mean * mean;
    float a = g2[c] * rsqrtf((float)var + EPSV);
    g_a2[c] = a;
    g_c2[c] = be2[c] - (float)mean * a;
}

// ---------------- K5: in-place activation z = relu(a2*y2 + c2) ----------------
__global__ void k_act(int N) {
    int c = blockIdx.y;
    size_t base = (size_t)c * N + (size_t)(blockIdx.x * blockDim.x + threadIdx.x) * 8;
    float a = g_a2[c], cc = g_c2[c];
    union { uint4 u; __half h[8]; } v;
    v.u = *(const uint4*)&g_y2h[base];
    #pragma unroll
    for (int j = 0; j < 8; j++)
        v.h[j] = __float2half_rn(fmaxf(fmaf(a, __half2float(v.h[j]), cc), 0.f));
    *(uint4*)&g_y2h[base] = v.u;
}

// ---------------- K6: decode output ----------------
__global__ void k_out(float* __restrict__ out, int B) {
    int i = blockIdx.x * blockDim.x + threadIdx.x;
    if (i < B * 1024) out[i] = funkey(g_pool2u[i]);
}

// ---------------- launch ----------------
extern "C" void kernel_launch(void* const* d_in, const int* in_sizes, int n_in,
                              void* d_out, int out_size) {
    const float* x   = (const float*)d_in[0];
    const int*   np  = (const int*)  d_in[1];
    const float* W1a = (const float*)d_in[2];
    const float* b1a = (const float*)d_in[3];
    const float* g1  = (const float*)d_in[4];
    const float* be1 = (const float*)d_in[5];
    const float* W1b = (const float*)d_in[6];
    const float* b1b = (const float*)d_in[7];
    const float* W2a = (const float*)d_in[8];
    const float* b2a = (const float*)d_in[9];
    const float* g2  = (const float*)d_in[10];
    const float* be2 = (const float*)d_in[11];
    const float* W2b = (const float*)d_in[12];
    const float* b2b = (const float*)d_in[13];
    int N = in_sizes[0] / 3;
    int B = in_sizes[1];
    if (N > MAXN) N = MAXN;

    cudaFuncSetAttribute(k_stage1_tc, cudaFuncAttributeMaxDynamicSharedMemorySize, S1_SMEM);
    cudaFuncSetAttribute(k_mma<0>, cudaFuncAttributeMaxDynamicSharedMemorySize, MMA_SMEM);
    cudaFuncSetAttribute(k_mma<1>, cudaFuncAttributeMaxDynamicSharedMemorySize, MMA_SMEM);

    k_init<<<32, 256>>>(np, B);
    k_segid<<<(N + 255) / 256, 256>>>(N, B);
    k_convW<<<2048, 256>>>(W2a, W2b, W1b);
    k_xstats<<<128, 256>>>(x, N);
    k_fold1<<<1, 128>>>(W1a, b1a, g1, be1, N, 128);
    k_stage1_tc<<<N / 128, 256, S1_SMEM>>>(x, b1b, N, B);
    k_decode1<<<(B * 256 + 255) / 256, 256>>>(B);
    k_symfold<<<512, 256>>>(W2a, B);
    dim3 g3(N / 256, 4);
    k_mma<0><<<g3, 256, MMA_SMEM>>>(b2a, N, B);
    k_bn2<<<2, 256>>>(g2, be2, N, N / 256);
    dim3 ga(N / 2048, 512);
    k_act<<<ga, 256>>>(N);
    dim3 g5(N / 256, 8);
    k_mma<1><<<g5, 256, MMA_SMEM>>>(b2b, N, B);
    k_out<<<(B * 1024 + 255) / 256, 256>>>((float*)d_out, B);
}

// round 11
// speedup vs baseline: 2.9136x; 1.4460x over previous
#include <cuda_runtime.h>
#include <cuda_fp16.h>
#include <math_constants.h>
#include <cstdint>

#define MAXN 131072
#define MAXB 32
#define EPSV 1e-5f

// ---------------- scratch (static device globals; no allocation) ----------------
__device__ __align__(16) __half g_mlph[256 * MAXN];   // mlp_feat fp16 [c][N]
__device__ __align__(16) __half g_y2h [512 * MAXN];   // raw y2 fp16 [c][N]
__device__ __align__(16) __half g_W2a_h[512 * 512];
__device__ __align__(16) __half g_W2b_h[1024 * 512];
__device__ __align__(16) __half g_W1b_h[256 * 128];
__device__ float    g_psum[512 * 1024];
__device__ float    g_psq [512 * 1024];
__device__ float    g_xpart[128 * 9];
__device__ float    g_Wf1[128 * 3];
__device__ float    g_bf1[128];
__device__ float    g_a2[512];
__device__ float    g_c2[512];
__device__ unsigned g_pool1u[MAXB * 256];
__device__ float    g_pool1f[MAXB * 256];
__device__ float    g_ysym[MAXB * 512];    // [seg][c] fp32 sym contribution
__device__ unsigned g_pool2u[MAXB * 1024];
__device__ int      g_off[MAXB + 1];
__device__ __align__(8) unsigned char g_segid[MAXN];

// monotonic float<->uint key for exact atomic max
__device__ __forceinline__ unsigned fkey(float f) {
    unsigned u = __float_as_uint(f);
    return (u & 0x80000000u) ? ~u : (u | 0x80000000u);
}
__device__ __forceinline__ float funkey(unsigned k) {
    return (k & 0x80000000u) ? __uint_as_float(k & 0x7fffffffu)
                             : __uint_as_float(~k);
}

// ---------------- PTX helpers ----------------
__device__ __forceinline__ unsigned smem_u32(const void* p) {
    return (unsigned)__cvta_generic_to_shared(p);
}
__device__ __forceinline__ void cp16(unsigned dst, const void* src) {
    asm volatile("cp.async.cg.shared.global [%0], [%1], 16;\n" :: "r"(dst), "l"(src));
}
__device__ __forceinline__ void cp_commit() { asm volatile("cp.async.commit_group;\n" ::); }
__device__ __forceinline__ void cp_wait0()  { asm volatile("cp.async.wait_group 0;\n" ::); }
__device__ __forceinline__ void cp_wait2()  { asm volatile("cp.async.wait_group 2;\n" ::); }
__device__ __forceinline__ void ldsm_x4(unsigned* r, unsigned addr) {
    asm volatile("ldmatrix.sync.aligned.m8n8.x4.shared.b16 {%0,%1,%2,%3},[%4];"
                 : "=r"(r[0]), "=r"(r[1]), "=r"(r[2]), "=r"(r[3]) : "r"(addr));
}
__device__ __forceinline__ void ldsm_x4_t(unsigned* r, unsigned addr) {
    asm volatile("ldmatrix.sync.aligned.m8n8.x4.trans.shared.b16 {%0,%1,%2,%3},[%4];"
                 : "=r"(r[0]), "=r"(r[1]), "=r"(r[2]), "=r"(r[3]) : "r"(addr));
}
__device__ __forceinline__ void mma16816(float* d, const unsigned* a, unsigned b0, unsigned b1) {
    asm volatile("mma.sync.aligned.m16n8k16.row.col.f32.f16.f16.f32 "
                 "{%0,%1,%2,%3},{%4,%5,%6,%7},{%8,%9},{%0,%1,%2,%3};"
                 : "+f"(d[0]), "+f"(d[1]), "+f"(d[2]), "+f"(d[3])
                 : "r"(a[0]), "r"(a[1]), "r"(a[2]), "r"(a[3]), "r"(b0), "r"(b1));
}

// ---------------- K0: offsets + pool init ----------------
__global__ void k_init(const int* npts, int B) {
    int tid = blockIdx.x * blockDim.x + threadIdx.x;
    if (blockIdx.x == 0 && threadIdx.x == 0) {
        int acc = 0; g_off[0] = 0;
        for (int b = 0; b < B; b++) { acc += npts[b]; g_off[b + 1] = acc; }
    }
    int stride = gridDim.x * blockDim.x;
    for (int i = tid; i < MAXB * 256;  i += stride) g_pool1u[i] = 0u;
    for (int i = tid; i < MAXB * 1024; i += stride) g_pool2u[i] = 0u;
}

__global__ void k_segid(int N, int B) {
    int n = blockIdx.x * blockDim.x + threadIdx.x;
    if (n >= N) return;
    int s = 0;
    while (s + 1 < B && g_off[s + 1] <= n) s++;
    g_segid[n] = (unsigned char)s;
}

__global__ void k_convW(const float* __restrict__ W2a, const float* __restrict__ W2b,
                        const float* __restrict__ W1b) {
    int i = blockIdx.x * blockDim.x + threadIdx.x;
    if (i < 512 * 512)  g_W2a_h[i] = __float2half_rn(W2a[i]);
    if (i < 1024 * 512) g_W2b_h[i] = __float2half_rn(W2b[i]);
    if (i < 256 * 128)  g_W1b_h[i] = __float2half_rn(W1b[i]);
}

// ---------------- K1a: x moments ----------------
__global__ void k_xstats(const float* __restrict__ x, int N) {
    float s0 = 0, s1 = 0, s2 = 0, q0 = 0, q1 = 0, q2 = 0, q3 = 0, q4 = 0, q5 = 0;
    int stride = gridDim.x * blockDim.x;
    for (int n = blockIdx.x * blockDim.x + threadIdx.x; n < N; n += stride) {
        float a = x[n], b = x[N + n], c = x[2 * N + n];
        s0 += a; s1 += b; s2 += c;
        q0 += a * a; q1 += a * b; q2 += a * c; q3 += b * b; q4 += b * c; q5 += c * c;
    }
    __shared__ float rb[256];
    float vals[9] = {s0, s1, s2, q0, q1, q2, q3, q4, q5};
    for (int v = 0; v < 9; v++) {
        rb[threadIdx.x] = vals[v];
        __syncthreads();
        for (int st = 128; st > 0; st >>= 1) {
            if (threadIdx.x < st) rb[threadIdx.x] += rb[threadIdx.x + st];
            __syncthreads();
        }
        if (threadIdx.x == 0) g_xpart[blockIdx.x * 9 + v] = rb[0];
        __syncthreads();
    }
}

// ---------------- K1b: fold BN1 into conv1a ----------------
__global__ void k_fold1(const float* __restrict__ W1a, const float* __restrict__ b1a,
                        const float* __restrict__ g1,  const float* __restrict__ be1,
                        int N, int nblocks) {
    __shared__ double S[9];
    __shared__ float mu[3], C[3][3];
    if (threadIdx.x < 9) {
        double a = 0;
        for (int b = 0; b < nblocks; b++) a += (double)g_xpart[b * 9 + threadIdx.x];
        S[threadIdx.x] = a;
    }
    __syncthreads();
    if (threadIdx.x == 0) {
        double invN = 1.0 / (double)N;
        double m0 = S[0] * invN, m1 = S[1] * invN, m2 = S[2] * invN;
        mu[0] = (float)m0; mu[1] = (float)m1; mu[2] = (float)m2;
        C[0][0] = (float)(S[3] * invN - m0 * m0);
        C[0][1] = (float)(S[4] * invN - m0 * m1);
        C[0][2] = (float)(S[5] * invN - m0 * m2);
        C[1][1] = (float)(S[6] * invN - m1 * m1);
        C[1][2] = (float)(S[7] * invN - m1 * m2);
        C[2][2] = (float)(S[8] * invN - m2 * m2);
        C[1][0] = C[0][1]; C[2][0] = C[0][2]; C[2][1] = C[1][2];
    }
    __syncthreads();
    int c = threadIdx.x;
    float w0 = W1a[c * 3], w1 = W1a[c * 3 + 1], w2 = W1a[c * 3 + 2];
    float mean1 = w0 * mu[0] + w1 * mu[1] + w2 * mu[2] + b1a[c];
    float var1 = w0 * w0 * C[0][0] + w1 * w1 * C[1][1] + w2 * w2 * C[2][2]
               + 2.f * (w0 * w1 * C[0][1] + w0 * w2 * C[0][2] + w1 * w2 * C[1][2]);
    float a = g1[c] * rsqrtf(var1 + EPSV);
    g_Wf1[c * 3 + 0] = a * w0;
    g_Wf1[c * 3 + 1] = a * w1;
    g_Wf1[c * 3 + 2] = a * w2;
    g_bf1[c] = a * (b1a[c] - mean1) + be1[c];
}

// ---------------- K2: stage1 via tensor cores ------------
#define S1_SMEM ((256 + 128) * 136 * 2)
__global__ void __launch_bounds__(256) k_stage1_tc(const float* __restrict__ x,
                                                   const float* __restrict__ b1b,
                                                   int N, int B) {
    extern __shared__ __align__(16) char dyn1[];
    __half* Ws = (__half*)dyn1;                       // [256][136]
    __half* Hs = (__half*)(dyn1 + 256 * 136 * 2);     // [128][136]
    __shared__ float xs[3][128];
    __shared__ float s_redA[256][2], s_redB[256][2];
    __shared__ int s_seg, s_bnd;

    const int tid = threadIdx.x, lane = tid & 31, wid = tid >> 5;
    const int wm = wid & 3, wn = wid >> 2;
    const int quad = lane >> 2, qlane = lane & 3;
    const int n0 = blockIdx.x * 128;

    #pragma unroll
    for (int i = 0; i < 16; i++) {
        int q = tid + i * 256;
        int r = q >> 4, c8 = (q & 15) * 8;
        cp16(smem_u32(&Ws[r * 136 + c8]), g_W1b_h + r * 128 + c8);
    }
    cp_commit();
    if (tid < 128) {
        xs[0][tid] = x[n0 + tid];
        xs[1][tid] = x[N + n0 + tid];
        xs[2][tid] = x[2 * N + n0 + tid];
    }
    if (tid == 0) {
        int s = g_segid[n0];
        s_seg = s; s_bnd = g_off[s + 1];
    }
    __syncthreads();
    {
        int c = tid >> 1, p0 = (tid & 1) * 64;
        float w0 = g_Wf1[c * 3], w1 = g_Wf1[c * 3 + 1], w2 = g_Wf1[c * 3 + 2];
        float b = g_bf1[c];
        #pragma unroll
        for (int j = 0; j < 64; j += 2) {
            int p = p0 + j;
            float h0 = fmaxf(b + w0 * xs[0][p]   + w1 * xs[1][p]   + w2 * xs[2][p],   0.f);
            float h1 = fmaxf(b + w0 * xs[0][p+1] + w1 * xs[1][p+1] + w2 * xs[2][p+1], 0.f);
            *(__half2*)&Hs[c * 136 + p] = __floats2half2_rn(h0, h1);
        }
    }
    cp_wait0();
    __syncthreads();

    float acc[4][8][4];
    #pragma unroll
    for (int m = 0; m < 4; m++)
        #pragma unroll
        for (int n = 0; n < 8; n++)
            #pragma unroll
            for (int v = 0; v < 4; v++) acc[m][n][v] = 0.f;

    unsigned aBase = smem_u32(Ws), bBase = smem_u32(Hs);
    unsigned aA0[4], bA0[4];
    #pragma unroll
    for (int mf = 0; mf < 4; mf++)
        aA0[mf] = aBase + (((wm * 64 + mf * 16 + (lane & 15)) * 136
                            + (lane >> 4) * 8) << 1);
    #pragma unroll
    for (int np = 0; np < 4; np++)
        bA0[np] = bBase + (((lane & 15) * 136 + wn * 64 + np * 16
                            + (lane >> 4) * 8) << 1);

    #pragma unroll
    for (int ks = 0; ks < 8; ks++) {
        unsigned af[4][4], bf[4][4];
        #pragma unroll
        for (int mf = 0; mf < 4; mf++) ldsm_x4(af[mf], aA0[mf] + ks * 32);
        #pragma unroll
        for (int np = 0; np < 4; np++) ldsm_x4_t(bf[np], bA0[np] + ks * 16 * 272);
        #pragma unroll
        for (int mf = 0; mf < 4; mf++)
            #pragma unroll
            for (int nf = 0; nf < 8; nf++)
                mma16816(acc[mf][nf], af[mf], bf[nf >> 1][(nf & 1) * 2],
                         bf[nf >> 1][(nf & 1) * 2 + 1]);
    }

    int bnd = s_bnd;
    bool hasB = (bnd < n0 + 128);
    #pragma unroll
    for (int mf = 0; mf < 4; mf++) {
        int cA = wm * 64 + mf * 16 + quad;
        int cB = cA + 8;
        float bA = b1b[cA], bB = b1b[cB];
        float a0 = -CUDART_INF_F, b0 = -CUDART_INF_F;
        float a1 = -CUDART_INF_F, b1 = -CUDART_INF_F;
        #pragma unroll
        for (int nf = 0; nf < 8; nf++) {
            int n = n0 + wn * 64 + nf * 8 + qlane * 2;
            float v0 = acc[mf][nf][0] + bA;
            float v1 = acc[mf][nf][1] + bA;
            float v2 = acc[mf][nf][2] + bB;
            float v3 = acc[mf][nf][3] + bB;
            *(__half2*)&g_mlph[(size_t)cA * N + n] = __floats2half2_rn(v0, v1);
            *(__half2*)&g_mlph[(size_t)cB * N + n] = __floats2half2_rn(v2, v3);
            if (n < bnd)     a0 = fmaxf(a0, v0); else b0 = fmaxf(b0, v0);
            if (n + 1 < bnd) a0 = fmaxf(a0, v1); else b0 = fmaxf(b0, v1);
            if (n < bnd)     a1 = fmaxf(a1, v2); else b1 = fmaxf(b1, v2);
            if (n + 1 < bnd) a1 = fmaxf(a1, v3); else b1 = fmaxf(b1, v3);
        }
        a0 = fmaxf(a0, __shfl_xor_sync(0xffffffff, a0, 1));
        a0 = fmaxf(a0, __shfl_xor_sync(0xffffffff, a0, 2));
        a1 = fmaxf(a1, __shfl_xor_sync(0xffffffff, a1, 1));
        a1 = fmaxf(a1, __shfl_xor_sync(0xffffffff, a1, 2));
        if (qlane == 0) { s_redA[cA][wn] = a0; s_redA[cB][wn] = a1; }
        if (hasB) {
            b0 = fmaxf(b0, __shfl_xor_sync(0xffffffff, b0, 1));
            b0 = fmaxf(b0, __shfl_xor_sync(0xffffffff, b0, 2));
            b1 = fmaxf(b1, __shfl_xor_sync(0xffffffff, b1, 1));
            b1 = fmaxf(b1, __shfl_xor_sync(0xffffffff, b1, 2));
            if (qlane == 0) { s_redB[cA][wn] = b0; s_redB[cB][wn] = b1; }
        }
    }
    __syncthreads();
    if (tid < 256) {
        float m = fmaxf(s_redA[tid][0], s_redA[tid][1]);
        atomicMax(&g_pool1u[s_seg * 256 + tid], fkey(m));
        if (hasB) {
            float mb = fmaxf(s_redB[tid][0], s_redB[tid][1]);
            atomicMax(&g_pool1u[(s_seg + 1) * 256 + tid], fkey(mb));
        }
    }
}

__global__ void k_decode1(int B) {
    int i = blockIdx.x * blockDim.x + threadIdx.x;
    if (i < B * 256) g_pool1f[i] = funkey(g_pool1u[i]);
}

// ---------------- sym fold: ysym[s][c] = W2a[c][256:512] . pool1[s] (fp32) ----
__global__ void k_symfold(const float* __restrict__ W2a, int B) {
    int c = blockIdx.x;
    int tid = threadIdx.x;
    int s = tid >> 3, kg = tid & 7;
    float acc = 0.f;
    if (s < B) {
        const float* w = W2a + (size_t)c * 512 + 256 + kg * 32;
        const float* p = g_pool1f + s * 256 + kg * 32;
        #pragma unroll
        for (int j = 0; j < 32; j++) acc += w[j] * p[j];
    }
    acc += __shfl_xor_sync(0xffffffff, acc, 1);
    acc += __shfl_xor_sync(0xffffffff, acc, 2);
    acc += __shfl_xor_sync(0xffffffff, acc, 4);
    if (kg == 0 && s < B) g_ysym[s * 512 + c] = acc;
}

// ---------------- big GEMMs: activation-resident blocking --------------------
// CTA = 128 points. B operand (activations, K x 128) resident in smem;
// weights streamed per 128-channel chunk via 4-stage cp.async (L2-hot).
#define G1_SMEM (256 * 136 * 2 + 4 * 128 * 24 * 2)
#define G2_SMEM (512 * 136 * 2 + 4 * 128 * 24 * 2)
template<int MODE>
__global__ void __launch_bounds__(256) k_big(const float* __restrict__ bias,
                                             int N, int B) {
    constexpr int KTOT = MODE ? 512 : 256;
    constexpr int KS   = KTOT / 16;
    constexpr int CCH  = MODE ? 8 : 4;
    constexpr int BRES_BYTES = KTOT * 136 * 2;

    extern __shared__ __align__(16) char dynm[];
    __half* bres = (__half*)dynm;
    const unsigned bBase = smem_u32(bres);
    const unsigned aBase0 = bBase + BRES_BYTES;
    __shared__ float s_redS[128][4], s_redQ[128][4];
    __shared__ int s_seg, s_bnd;

    const int tid = threadIdx.x, lane = tid & 31, wid = tid >> 5;
    const int wn = wid & 3, wm = wid >> 2;     // 2 c-warps x 4 n-warps (64c x 32n)
    const int quad = lane >> 2, qlane = lane & 3;
    const int n0 = blockIdx.x * 128;
    const __half* __restrict__ Aw   = MODE ? g_W2b_h : g_W2a_h;  // row stride 512
    const __half* __restrict__ Bsrc = MODE ? g_y2h   : g_mlph;

    if (tid == 0) {
        int s = g_segid[n0];
        s_seg = s; s_bnd = g_off[s + 1];
    }

    // ---- resident B preload: KTOT rows x 128 halves, row stride 136 halves ----
    // cp16 count = KTOT rows * 16 chunks = KTOT*16; per iter 256 -> KTOT/16 iters
    #pragma unroll
    for (int i = 0; i < KTOT / 16; i++) {
        int q = tid + i * 256;
        int row = q >> 4, c8 = (q & 15) * 8;
        cp16(bBase + ((row * 136 + c8) << 1), Bsrc + (size_t)row * N + n0 + c8);
    }
    cp_commit(); cp_wait0(); __syncthreads();
    if (MODE == 1) {   // BN2 + ReLU in smem
        #pragma unroll
        for (int t = 0; t < 2; t++) {
            int row = tid + t * 256;
            float a = g_a2[row], cc = g_c2[row];
            __half2* rp = (__half2*)&bres[row * 136];
            #pragma unroll
            for (int j = 0; j < 64; j++) {
                float2 f = __half22float2(rp[j]);
                rp[j] = __floats2half2_rn(fmaxf(fmaf(a, f.x, cc), 0.f),
                                          fmaxf(fmaf(a, f.y, cc), 0.f));
            }
        }
        __syncthreads();
    }
    const int bnd = s_bnd;

    const unsigned aOffW = (((wm * 64 + (lane & 15)) * 24 + (lane >> 4) * 8) << 1);
    unsigned bA0[2];
    #pragma unroll
    for (int np = 0; np < 2; np++)
        bA0[np] = bBase + (((lane & 15) * 136 + wn * 32 + np * 16
                            + (lane >> 4) * 8) << 1);

    for (int ch = 0; ch < CCH; ch++) {
        const int c0 = ch * 128;
        auto issueA = [&](int ks, int s) {
            int row = tid >> 1, c8 = (tid & 1) * 8;
            cp16(aBase0 + s * 6144 + ((row * 24 + c8) << 1),
                 Aw + (size_t)(c0 + row) * 512 + ks * 16 + c8);
        };
        issueA(0, 0); cp_commit();
        issueA(1, 1); cp_commit();
        issueA(2, 2); cp_commit();

        float acc[4][4][4];
        #pragma unroll
        for (int m = 0; m < 4; m++)
            #pragma unroll
            for (int n = 0; n < 4; n++)
                #pragma unroll
                for (int v = 0; v < 4; v++) acc[m][n][v] = 0.f;

        for (int ks = 0; ks < KS; ks++) {
            cp_wait2();
            __syncthreads();
            if (ks + 3 < KS) issueA(ks + 3, (ks + 3) & 3);
            cp_commit();
            unsigned aS = aBase0 + (ks & 3) * 6144 + aOffW;
            unsigned af[4][4], bf[2][4];
            #pragma unroll
            for (int mf = 0; mf < 4; mf++) ldsm_x4(af[mf], aS + mf * 768);
            #pragma unroll
            for (int np = 0; np < 2; np++) ldsm_x4_t(bf[np], bA0[np] + ks * 4352);
            #pragma unroll
            for (int mf = 0; mf < 4; mf++)
                #pragma unroll
                for (int nf = 0; nf < 4; nf++)
                    mma16816(acc[mf][nf], af[mf], bf[nf >> 1][(nf & 1) * 2],
                             bf[nf >> 1][(nf & 1) * 2 + 1]);
        }
        __syncthreads();

        // ---- per-chunk epilogue ----
        if (MODE == 0) {
            int nb = blockIdx.x;
            int s2 = (s_seg + 1 < B) ? s_seg + 1 : B - 1;
            #pragma unroll
            for (int mf = 0; mf < 4; mf++) {
                int cA = c0 + wm * 64 + mf * 16 + quad;
                int cB = cA + 8;
                float bA = bias[cA], bB = bias[cB];
                float yA1 = g_ysym[s_seg * 512 + cA], yA2 = g_ysym[s2 * 512 + cA];
                float yB1 = g_ysym[s_seg * 512 + cB], yB2 = g_ysym[s2 * 512 + cB];
                float sA = 0, qA = 0, sB = 0, qB = 0;
                #pragma unroll
                for (int nf = 0; nf < 4; nf++) {
                    int n = n0 + wn * 32 + nf * 8 + qlane * 2;
                    bool i0 = n < bnd, i1 = (n + 1) < bnd;
                    float v0 = acc[mf][nf][0] + bA + (i0 ? yA1 : yA2);
                    float v1 = acc[mf][nf][1] + bA + (i1 ? yA1 : yA2);
                    float v2 = acc[mf][nf][2] + bB + (i0 ? yB1 : yB2);
                    float v3 = acc[mf][nf][3] + bB + (i1 ? yB1 : yB2);
                    *(__half2*)&g_y2h[(size_t)cA * N + n] = __floats2half2_rn(v0, v1);
                    *(__half2*)&g_y2h[(size_t)cB * N + n] = __floats2half2_rn(v2, v3);
                    sA += v0 + v1; qA += v0 * v0 + v1 * v1;
                    sB += v2 + v3; qB += v2 * v2 + v3 * v3;
                }
                sA += __shfl_xor_sync(0xffffffff, sA, 1);
                sA += __shfl_xor_sync(0xffffffff, sA, 2);
                qA += __shfl_xor_sync(0xffffffff, qA, 1);
                qA += __shfl_xor_sync(0xffffffff, qA, 2);
                sB += __shfl_xor_sync(0xffffffff, sB, 1);
                sB += __shfl_xor_sync(0xffffffff, sB, 2);
                qB += __shfl_xor_sync(0xffffffff, qB, 1);
                qB += __shfl_xor_sync(0xffffffff, qB, 2);
                if (qlane == 0) {
                    int rA = wm * 64 + mf * 16 + quad, rB = rA + 8;
                    s_redS[rA][wn] = sA; s_redQ[rA][wn] = qA;
                    s_redS[rB][wn] = sB; s_redQ[rB][wn] = qB;
                }
            }
            __syncthreads();
            if (tid < 128) {
                float s = s_redS[tid][0] + s_redS[tid][1] + s_redS[tid][2] + s_redS[tid][3];
                float q = s_redQ[tid][0] + s_redQ[tid][1] + s_redQ[tid][2] + s_redQ[tid][3];
                g_psum[(size_t)(c0 + tid) * 1024 + nb] = s;
                g_psq [(size_t)(c0 + tid) * 1024 + nb] = q;
            }
            __syncthreads();
        } else {
            bool hasB = (bnd < n0 + 128);
            #pragma unroll
            for (int mf = 0; mf < 4; mf++) {
                int cA = c0 + wm * 64 + mf * 16 + quad;
                float bA = bias[cA], bB = bias[cA + 8];
                float a0 = -CUDART_INF_F, b0 = -CUDART_INF_F;
                float a1 = -CUDART_INF_F, b1 = -CUDART_INF_F;
                #pragma unroll
                for (int nf = 0; nf < 4; nf++) {
                    int n = n0 + wn * 32 + nf * 8 + qlane * 2;
                    float v0 = acc[mf][nf][0] + bA;
                    float v1 = acc[mf][nf][1] + bA;
                    float v2 = acc[mf][nf][2] + bB;
                    float v3 = acc[mf][nf][3] + bB;
                    if (n < bnd)     a0 = fmaxf(a0, v0); else b0 = fmaxf(b0, v0);
                    if (n + 1 < bnd) a0 = fmaxf(a0, v1); else b0 = fmaxf(b0, v1);
                    if (n < bnd)     a1 = fmaxf(a1, v2); else b1 = fmaxf(b1, v2);
                    if (n + 1 < bnd) a1 = fmaxf(a1, v3); else b1 = fmaxf(b1, v3);
                }
                a0 = fmaxf(a0, __shfl_xor_sync(0xffffffff, a0, 1));
                a0 = fmaxf(a0, __shfl_xor_sync(0xffffffff, a0, 2));
                a1 = fmaxf(a1, __shfl_xor_sync(0xffffffff, a1, 1));
                a1 = fmaxf(a1, __shfl_xor_sync(0xffffffff, a1, 2));
                if (qlane == 0) {
                    int rA = wm * 64 + mf * 16 + quad, rB = rA + 8;
                    s_redS[rA][wn] = a0; s_redS[rB][wn] = a1;
                }
                if (hasB) {
                    b0 = fmaxf(b0, __shfl_xor_sync(0xffffffff, b0, 1));
                    b0 = fmaxf(b0, __shfl_xor_sync(0xffffffff, b0, 2));
                    b1 = fmaxf(b1, __shfl_xor_sync(0xffffffff, b1, 1));
                    b1 = fmaxf(b1, __shfl_xor_sync(0xffffffff, b1, 2));
                    if (qlane == 0) {
                        int rA = wm * 64 + mf * 16 + quad, rB = rA + 8;
                        s_redQ[rA][wn] = b0; s_redQ[rB][wn] = b1;
                    }
                }
            }
            __syncthreads();
            if (tid < 128) {
                float m = fmaxf(fmaxf(s_redS[tid][0], s_redS[tid][1]),
                                fmaxf(s_redS[tid][2], s_redS[tid][3]));
                atomicMax(&g_pool2u[s_seg * 1024 + c0 + tid], fkey(m));
                if (hasB) {
                    float mb = fmaxf(fmaxf(s_redQ[tid][0], s_redQ[tid][1]),
                                     fmaxf(s_redQ[tid][2], s_redQ[tid][3]));
                    atomicMax(&g_pool2u[(s_seg + 1) * 1024 + c0 + tid], fkey(mb));
                }
            }
            __syncthreads();
        }
    }
}

// ---------------- K4: reduce BN2 stats (parallel, deterministic) --------------
__global__ void k_bn2(const float* __restrict__ g2, const float* __restrict__ be2,
                      int N, int NB) {
    int c = blockIdx.x;
    int tid = threadIdx.x;
    double s = 0, q = 0;
    for (int nb = tid; nb < NB; nb += 256) {
        s += (double)g_psum[(size_t)c * 1024 + nb];
        q += (double)g_psq [(size_t)c * 1024 + nb];
    }
    __shared__ double rs[256], rq[256];
    rs[tid] = s; rq[tid] = q;
    __syncthreads();
    for (int st = 128; st > 0; st >>= 1) {
        if (tid < st) { rs[tid] += rs[tid + st]; rq[tid] += rq[tid + st]; }
        __syncthreads();
    }
    if (tid == 0) {
        double mean = rs[0] / (double)N;
        double var  = rq[0] / (double)N - mean * mean;
        float a = g2[c] * rsqrtf((float)var + EPSV);
        g_a2[c] = a;
        g_c2[c] = be2[c] - (float)mean * a;
    }
}

// ---------------- K6: decode output ----------------
__global__ void k_out(float* __restrict__ out, int B) {
    int i = blockIdx.x * blockDim.x + threadIdx.x;
    if (i < B * 1024) out[i] = funkey(g_pool2u[i]);
}

// ---------------- launch ----------------
extern "C" void kernel_launch(void* const* d_in, const int* in_sizes, int n_in,
                              void* d_out, int out_size) {
    const float* x   = (const float*)d_in[0];
    const int*   np  = (const int*)  d_in[1];
    const float* W1a = (const float*)d_in[2];
    const float* b1a = (const float*)d_in[3];
    const float* g1  = (const float*)d_in[4];
    const float* be1 = (const float*)d_in[5];
    const float* W1b = (const float*)d_in[6];
    const float* b1b = (const float*)d_in[7];
    const float* W2a = (const float*)d_in[8];
    const float* b2a = (const float*)d_in[9];
    const float* g2  = (const float*)d_in[10];
    const float* be2 = (const float*)d_in[11];
    const float* W2b = (const float*)d_in[12];
    const float* b2b = (const float*)d_in[13];
    int N = in_sizes[0] / 3;
    int B = in_sizes[1];
    if (N > MAXN) N = MAXN;

    cudaFuncSetAttribute(k_stage1_tc, cudaFuncAttributeMaxDynamicSharedMemorySize, S1_SMEM);
    cudaFuncSetAttribute(k_big<0>, cudaFuncAttributeMaxDynamicSharedMemorySize, G1_SMEM);
    cudaFuncSetAttribute(k_big<1>, cudaFuncAttributeMaxDynamicSharedMemorySize, G2_SMEM);

    k_init<<<32, 256>>>(np, B);
    k_segid<<<(N + 255) / 256, 256>>>(N, B);
    k_convW<<<2048, 256>>>(W2a, W2b, W1b);
    k_xstats<<<128, 256>>>(x, N);
    k_fold1<<<1, 128>>>(W1a, b1a, g1, be1, N, 128);
    k_stage1_tc<<<N / 128, 256, S1_SMEM>>>(x, b1b, N, B);
    k_decode1<<<(B * 256 + 255) / 256, 256>>>(B);
    k_symfold<<<512, 256>>>(W2a, B);
    k_big<0><<<N / 128, 256, G1_SMEM>>>(b2a, N, B);
    k_bn2<<<512, 256>>>(g2, be2, N, N / 128);
    k_big<1><<<N / 128, 256, G2_SMEM>>>(b2b, N, B);
    k_out<<<(B * 1024 + 255) / 256, 256>>>((float*)d_out, B);
}